// round 1
// baseline (speedup 1.0000x reference)
#include <cuda_runtime.h>
#include <math.h>

// ---------------- problem constants ----------------
#define BB 2
#define SS 2048
#define DD 1024
#define HH 16
#define DHD 64
#define NROW (BB*SS)      // 4096
#define RA 32
#define HR (HH*RA)        // 512
#define R_OUT 512
#define II 4096
#define R_FC 512

// ---------------- device scratch (bss, no allocation) ----------------
__device__ float g_x [NROW*DD];
__device__ float g_Qr[NROW*HR];
__device__ float g_Kr[NROW*HR];
__device__ float g_Vr[NROW*HR];
__device__ float g_Q [NROW*DD];
__device__ float g_K [NROW*DD];
__device__ float g_V [NROW*DD];
__device__ float g_Yh[NROW*DD];
__device__ float g_Y [NROW*DD];
__device__ float g_T1[NROW*R_OUT];
__device__ float g_h [NROW*DD];
__device__ float g_z [NROW*DD];
__device__ float g_T2[NROW*R_FC];
__device__ float g_H1[NROW*II];
__device__ float g_T3[NROW*R_FC];

// ---------------- layernorm: one block per row, 256 threads ----------------
__global__ void ln_kernel(const float* __restrict__ in, float* __restrict__ out,
                          const float* __restrict__ gw, const float* __restrict__ bw) {
    int row = blockIdx.x;
    int tid = threadIdx.x;
    const float4* x4 = (const float4*)(in + (size_t)row * DD);
    float4 v = x4[tid];
    __shared__ float red[8];
    __shared__ float stat[2];
    float s = v.x + v.y + v.z + v.w;
    #pragma unroll
    for (int o = 16; o; o >>= 1) s += __shfl_xor_sync(0xffffffffu, s, o);
    if ((tid & 31) == 0) red[tid >> 5] = s;
    __syncthreads();
    if (tid < 32) {
        float t = (tid < 8) ? red[tid] : 0.f;
        #pragma unroll
        for (int o = 4; o; o >>= 1) t += __shfl_xor_sync(0xffffffffu, t, o);
        if (tid == 0) stat[0] = t * (1.0f / DD);
    }
    __syncthreads();
    float mu = stat[0];
    float a = v.x - mu, b = v.y - mu, c = v.z - mu, d = v.w - mu;
    float s2 = a*a + b*b + c*c + d*d;
    #pragma unroll
    for (int o = 16; o; o >>= 1) s2 += __shfl_xor_sync(0xffffffffu, s2, o);
    if ((tid & 31) == 0) red[tid >> 5] = s2;
    __syncthreads();
    if (tid < 32) {
        float t = (tid < 8) ? red[tid] : 0.f;
        #pragma unroll
        for (int o = 4; o; o >>= 1) t += __shfl_xor_sync(0xffffffffu, t, o);
        if (tid == 0) stat[1] = rsqrtf(t * (1.0f / DD) + 1e-5f);
    }
    __syncthreads();
    float rs = stat[1];
    float4 g4 = ((const float4*)gw)[tid];
    float4 b4 = ((const float4*)bw)[tid];
    float4 o4 = make_float4(a*rs*g4.x + b4.x, b*rs*g4.y + b4.y,
                            c*rs*g4.z + b4.z, d*rs*g4.w + b4.w);
    ((float4*)(out + (size_t)row * DD))[tid] = o4;
}

// ---------------- generic tiled SGEMM: C[M,N] = A[M,K] @ B[K,N] (+epilogue) ----
// BM=BN=128, BK=8, 256 threads, 8x8 per thread. M,N mult of 128; K mult of 8.
template<bool BIAS, bool GELU, bool RES>
__global__ void __launch_bounds__(256, 2)
sgemm(const float* __restrict__ A, const float* __restrict__ Bm,
      float* __restrict__ C, const float* __restrict__ bias,
      const float* __restrict__ res, int M, int N, int K) {
    __shared__ float As[8][128];
    __shared__ float Bs[8][128];
    int bm = blockIdx.y * 128, bn = blockIdx.x * 128;
    int tid = threadIdx.x;
    int tx = tid & 15, ty = tid >> 4;

    float acc[8][8];
    #pragma unroll
    for (int i = 0; i < 8; i++)
        #pragma unroll
        for (int j = 0; j < 8; j++) acc[i][j] = 0.f;

    int arow = tid >> 1;          // 0..127
    int acol = (tid & 1) * 4;     // 0 or 4
    int brow = tid >> 5;          // 0..7
    int bcol = (tid & 31) * 4;    // 0..124
    const float* Aptr = A + (size_t)(bm + arow) * K + acol;
    const float* Bptr = Bm + (size_t)brow * N + bn + bcol;

    for (int k0 = 0; k0 < K; k0 += 8) {
        float4 av = *(const float4*)Aptr;  Aptr += 8;
        float4 bv = *(const float4*)Bptr;  Bptr += (size_t)8 * N;
        As[acol + 0][arow] = av.x;
        As[acol + 1][arow] = av.y;
        As[acol + 2][arow] = av.z;
        As[acol + 3][arow] = av.w;
        *(float4*)&Bs[brow][bcol] = bv;
        __syncthreads();
        #pragma unroll
        for (int k = 0; k < 8; k++) {
            float af[8], bf[8];
            *(float4*)(af)     = *(const float4*)&As[k][ty * 8];
            *(float4*)(af + 4) = *(const float4*)&As[k][ty * 8 + 4];
            *(float4*)(bf)     = *(const float4*)&Bs[k][tx * 8];
            *(float4*)(bf + 4) = *(const float4*)&Bs[k][tx * 8 + 4];
            #pragma unroll
            for (int i = 0; i < 8; i++)
                #pragma unroll
                for (int j = 0; j < 8; j++)
                    acc[i][j] = fmaf(af[i], bf[j], acc[i][j]);
        }
        __syncthreads();
    }

    #pragma unroll
    for (int i = 0; i < 8; i++) {
        int row = bm + ty * 8 + i;
        float* crow = C + (size_t)row * N + bn + tx * 8;
        const float* rrow = RES ? (res + (size_t)row * N + bn + tx * 8) : nullptr;
        #pragma unroll
        for (int j = 0; j < 8; j++) {
            float v = acc[i][j];
            if (BIAS) v += bias[bn + tx * 8 + j];
            if (GELU) v = 0.5f * v * (1.0f + erff(v * 0.70710678118654752f));
            if (RES)  v += rrow[j];
            crow[j] = v;
        }
    }
}

// ---------------- per-head rank expansion: [4096,32]@[32,64]+bias -> [B,H,S,DH]
__global__ void expand_heads(const float* __restrict__ Xr, const float* __restrict__ Vh,
                             const float* __restrict__ bias, float* __restrict__ out) {
    int bh = blockIdx.y;            // b*H + h
    int b  = bh / HH;
    int h  = bh % HH;
    int s0 = blockIdx.x * 64;
    __shared__ float Vs[RA][DHD];   // 32x64
    __shared__ float Xs[64][RA];    // 64x32
    int tid = threadIdx.x;
    const float* vp = Vh + (size_t)h * RA * DHD;
    for (int i = tid; i < RA * DHD / 4; i += 256)
        ((float4*)Vs)[i] = ((const float4*)vp)[i];
    for (int i = tid; i < 64 * RA / 4; i += 256) {
        int r = i >> 3, c4 = (i & 7) << 2;
        *(float4*)&Xs[r][c4] =
            *(const float4*)(Xr + (size_t)(b * SS + s0 + r) * HR + h * RA + c4);
    }
    __syncthreads();
    for (int i = tid; i < 64 * DHD; i += 256) {
        int sl = i >> 6, e = i & 63;
        float acc = bias[h * DHD + e];
        #pragma unroll
        for (int r = 0; r < RA; r++) acc = fmaf(Xs[sl][r], Vs[r][e], acc);
        out[((size_t)bh * SS + s0 + sl) * DHD + e] = acc;
    }
}

// ---------------- flash attention (causal), 64x64 tiles, DH=64, fp32 --------
#define FLD 68
__global__ void __launch_bounds__(256, 2)
flash_attn(const float* __restrict__ Q, const float* __restrict__ K,
           const float* __restrict__ V, float* __restrict__ O) {
    extern __shared__ float sm[];
    float* Qs = sm;
    float* Ks = Qs + 64 * FLD;
    float* Vs = Ks + 64 * FLD;
    float* Ps = Vs + 64 * FLD;
    int bh = blockIdx.y;
    int m0 = (gridDim.x - 1 - blockIdx.x) * 64;   // heavy tiles launch first
    const float* Qg = Q + ((size_t)bh * SS + m0) * DHD;
    const float* Kg = K + (size_t)bh * SS * DHD;
    const float* Vg = V + (size_t)bh * SS * DHD;
    int tid = threadIdx.x;
    int tr = tid >> 4, tc = tid & 15;   // 4 rows / 4 cols per thread

    for (int i = tid; i < 1024; i += 256) {
        int r = i >> 4, c4 = (i & 15) << 2;
        *(float4*)(Qs + r * FLD + c4) = *(const float4*)(Qg + (size_t)r * DHD + c4);
    }
    float o[4][4];
    float m_i[4], l_i[4];
    #pragma unroll
    for (int i = 0; i < 4; i++) {
        m_i[i] = -1e30f; l_i[i] = 0.f;
        #pragma unroll
        for (int j = 0; j < 4; j++) o[i][j] = 0.f;
    }

    for (int n0 = 0; n0 <= m0; n0 += 64) {
        __syncthreads();
        for (int i = tid; i < 1024; i += 256) {
            int r = i >> 4, c4 = (i & 15) << 2;
            *(float4*)(Ks + r * FLD + c4) = *(const float4*)(Kg + (size_t)(n0 + r) * DHD + c4);
            *(float4*)(Vs + r * FLD + c4) = *(const float4*)(Vg + (size_t)(n0 + r) * DHD + c4);
        }
        __syncthreads();

        float s[4][4];
        #pragma unroll
        for (int i = 0; i < 4; i++)
            #pragma unroll
            for (int j = 0; j < 4; j++) s[i][j] = 0.f;
        #pragma unroll 8
        for (int k = 0; k < 64; k++) {
            float qf[4], kf[4];
            #pragma unroll
            for (int i = 0; i < 4; i++) qf[i] = Qs[(tr * 4 + i) * FLD + k];
            #pragma unroll
            for (int j = 0; j < 4; j++) kf[j] = Ks[(tc * 4 + j) * FLD + k];
            #pragma unroll
            for (int i = 0; i < 4; i++)
                #pragma unroll
                for (int j = 0; j < 4; j++) s[i][j] = fmaf(qf[i], kf[j], s[i][j]);
        }
        const float scale = 0.125f;   // 1/sqrt(64)
        bool diag = (n0 == m0);
        float pr[4][4], alpha[4];
        #pragma unroll
        for (int i = 0; i < 4; i++) {
            int grow = tr * 4 + i;
            float mx = -1e30f;
            #pragma unroll
            for (int j = 0; j < 4; j++) {
                float v = s[i][j] * scale;
                if (diag && (tc * 4 + j) > grow) v = -1e30f;
                s[i][j] = v;
                mx = fmaxf(mx, v);
            }
            #pragma unroll
            for (int off = 8; off; off >>= 1)
                mx = fmaxf(mx, __shfl_xor_sync(0xffffffffu, mx, off));
            float newm = fmaxf(m_i[i], mx);
            float a = __expf(m_i[i] - newm);
            float rs = 0.f;
            #pragma unroll
            for (int j = 0; j < 4; j++) {
                float p = __expf(s[i][j] - newm);
                pr[i][j] = p; rs += p;
            }
            #pragma unroll
            for (int off = 8; off; off >>= 1)
                rs += __shfl_xor_sync(0xffffffffu, rs, off);
            l_i[i] = l_i[i] * a + rs;
            m_i[i] = newm;
            alpha[i] = a;
        }
        #pragma unroll
        for (int i = 0; i < 4; i++)
            #pragma unroll
            for (int j = 0; j < 4; j++) o[i][j] *= alpha[i];
        #pragma unroll
        for (int i = 0; i < 4; i++)
            #pragma unroll
            for (int j = 0; j < 4; j++)
                Ps[(tr * 4 + i) * FLD + tc * 4 + j] = pr[i][j];
        __syncthreads();
        #pragma unroll 8
        for (int n = 0; n < 64; n++) {
            float pv[4], vv[4];
            #pragma unroll
            for (int i = 0; i < 4; i++) pv[i] = Ps[(tr * 4 + i) * FLD + n];
            #pragma unroll
            for (int j = 0; j < 4; j++) vv[j] = Vs[n * FLD + tc * 4 + j];
            #pragma unroll
            for (int i = 0; i < 4; i++)
                #pragma unroll
                for (int j = 0; j < 4; j++) o[i][j] = fmaf(pv[i], vv[j], o[i][j]);
        }
    }

    float* Og = O + ((size_t)bh * SS + m0) * DHD;
    #pragma unroll
    for (int i = 0; i < 4; i++) {
        float inv = 1.0f / l_i[i];
        #pragma unroll
        for (int j = 0; j < 4; j++)
            Og[(size_t)(tr * 4 + i) * DHD + tc * 4 + j] = o[i][j] * inv;
    }
}

// ---------------- merge heads: Yh[b,h,s,e] -> Y[b,s,h*64+e] -----------------
__global__ void merge_heads(const float* __restrict__ Yh, float* __restrict__ Y) {
    size_t idx = (size_t)blockIdx.x * 256 + threadIdx.x;  // float4 index
    size_t row = idx >> 8;             // /256 float4 per row (D=1024)
    int c4 = (int)(idx & 255) << 2;
    int b_ = (int)(row >> 11);
    int s_ = (int)(row & 2047);
    int h_ = c4 >> 6;
    int e  = c4 & 63;
    float4 v = *(const float4*)(Yh + (((size_t)(b_ * HH + h_) * SS + s_) * DHD + e));
    *(float4*)(Y + row * DD + c4) = v;
}

// ---------------- host launcher ----------------
extern "C" void kernel_launch(void* const* d_in, const int* in_sizes, int n_in,
                              void* d_out, int out_size) {
    const float* hidden = (const float*)d_in[0];
    const float* ln1_g  = (const float*)d_in[1];
    const float* ln1_b  = (const float*)d_in[2];
    const float* ln2_g  = (const float*)d_in[3];
    const float* ln2_b  = (const float*)d_in[4];
    const float* q_U = (const float*)d_in[5];
    const float* q_V = (const float*)d_in[6];
    const float* q_b = (const float*)d_in[7];
    const float* k_U = (const float*)d_in[8];
    const float* k_V = (const float*)d_in[9];
    const float* k_b = (const float*)d_in[10];
    const float* v_U = (const float*)d_in[11];
    const float* v_V = (const float*)d_in[12];
    const float* v_b = (const float*)d_in[13];
    const float* out_U = (const float*)d_in[14];
    const float* out_V = (const float*)d_in[15];
    const float* out_b = (const float*)d_in[16];
    const float* fc1_U = (const float*)d_in[17];
    const float* fc1_V = (const float*)d_in[18];
    const float* fc1_b = (const float*)d_in[19];
    const float* fc2_U = (const float*)d_in[20];
    const float* fc2_V = (const float*)d_in[21];
    const float* fc2_b = (const float*)d_in[22];
    float* out = (float*)d_out;

    float *x, *Qr, *Kr, *Vr, *Qb, *Kb, *Vb, *Yh, *Y, *T1, *hb, *z, *T2, *H1, *T3;
    cudaGetSymbolAddress((void**)&x,  g_x);
    cudaGetSymbolAddress((void**)&Qr, g_Qr);
    cudaGetSymbolAddress((void**)&Kr, g_Kr);
    cudaGetSymbolAddress((void**)&Vr, g_Vr);
    cudaGetSymbolAddress((void**)&Qb, g_Q);
    cudaGetSymbolAddress((void**)&Kb, g_K);
    cudaGetSymbolAddress((void**)&Vb, g_V);
    cudaGetSymbolAddress((void**)&Yh, g_Yh);
    cudaGetSymbolAddress((void**)&Y,  g_Y);
    cudaGetSymbolAddress((void**)&T1, g_T1);
    cudaGetSymbolAddress((void**)&hb, g_h);
    cudaGetSymbolAddress((void**)&z,  g_z);
    cudaGetSymbolAddress((void**)&T2, g_T2);
    cudaGetSymbolAddress((void**)&H1, g_H1);
    cudaGetSymbolAddress((void**)&T3, g_T3);

    int fa_smem = 4 * 64 * FLD * sizeof(float);  // 69632 bytes
    cudaFuncSetAttribute(flash_attn, cudaFuncAttributeMaxDynamicSharedMemorySize, fa_smem);

    // 1. LN1
    ln_kernel<<<NROW, 256>>>(hidden, x, ln1_g, ln1_b);
    // 2. rank projections x @ {q,k,v}_U  -> [4096, 512]
    sgemm<false,false,false><<<dim3(HR/128, NROW/128), 256>>>(x, q_U, Qr, nullptr, nullptr, NROW, HR, DD);
    sgemm<false,false,false><<<dim3(HR/128, NROW/128), 256>>>(x, k_U, Kr, nullptr, nullptr, NROW, HR, DD);
    sgemm<false,false,false><<<dim3(HR/128, NROW/128), 256>>>(x, v_U, Vr, nullptr, nullptr, NROW, HR, DD);
    // 3. per-head expansion -> [B,H,S,DH]
    expand_heads<<<dim3(SS/64, BB*HH), 256>>>(Qr, q_V, q_b, Qb);
    expand_heads<<<dim3(SS/64, BB*HH), 256>>>(Kr, k_V, k_b, Kb);
    expand_heads<<<dim3(SS/64, BB*HH), 256>>>(Vr, v_V, v_b, Vb);
    // 4. causal flash attention
    flash_attn<<<dim3(SS/64, BB*HH), 256, fa_smem>>>(Qb, Kb, Vb, Yh);
    // 5. merge heads
    merge_heads<<<(NROW*DD/4)/256, 256>>>(Yh, Y);
    // 6. out projection + residual
    sgemm<false,false,false><<<dim3(R_OUT/128, NROW/128), 256>>>(Y, out_U, T1, nullptr, nullptr, NROW, R_OUT, DD);
    sgemm<true,false,true><<<dim3(DD/128, NROW/128), 256>>>(T1, out_V, hb, out_b, hidden, NROW, DD, R_OUT);
    // 7. LN2
    ln_kernel<<<NROW, 256>>>(hb, z, ln2_g, ln2_b);
    // 8. MLP
    sgemm<false,false,false><<<dim3(R_FC/128, NROW/128), 256>>>(z, fc1_U, T2, nullptr, nullptr, NROW, R_FC, DD);
    sgemm<true,true,false><<<dim3(II/128, NROW/128), 256>>>(T2, fc1_V, H1, fc1_b, nullptr, NROW, II, R_FC);
    sgemm<false,false,false><<<dim3(R_FC/128, NROW/128), 256>>>(H1, fc2_U, T3, nullptr, nullptr, NROW, R_FC, II);
    sgemm<true,false,true><<<dim3(DD/128, NROW/128), 256>>>(T3, fc2_V, out, fc2_b, hb, NROW, DD, R_FC);
}

// round 3
// speedup vs baseline: 1.7506x; 1.7506x over previous
#include <cuda_runtime.h>
#include <cuda_bf16.h>
#include <math.h>
#include <stdint.h>

// ---------------- problem constants ----------------
#define BB 2
#define SS 2048
#define DD 1024
#define HH 16
#define DHD 64
#define NROW (BB*SS)      // 4096
#define RA 32
#define HR 512            // H*RA
#define HR3 1536          // fused qkv width
#define R_OUT 512
#define II 4096
#define R_FC 512

// ---------------- device scratch (bss, no allocation) ----------------
__device__ float g_x   [NROW*DD];
__device__ float g_QKVr[NROW*HR3];
__device__ float g_Q   [NROW*DD];
__device__ float g_K   [NROW*DD];
__device__ float g_V   [NROW*DD];
__device__ float g_Yh  [NROW*DD];
__device__ float g_Y   [NROW*DD];
__device__ float g_T1  [NROW*R_OUT];
__device__ float g_h   [NROW*DD];
__device__ float g_z   [NROW*DD];
__device__ float g_T2  [NROW*R_FC];
__device__ float g_H1  [NROW*II];
__device__ float g_T3  [NROW*R_FC];

// bf16 hi/lo split buffers (aligned for 16B cp.async)
__device__ __align__(1024) __nv_bfloat16 g_Ah[NROW*II];
__device__ __align__(1024) __nv_bfloat16 g_Al[NROW*II];
__device__ __align__(1024) __nv_bfloat16 g_Bqkvh[HR3*DD];
__device__ __align__(1024) __nv_bfloat16 g_Bqkvl[HR3*DD];
__device__ __align__(1024) __nv_bfloat16 g_Bouh[R_OUT*DD],  g_Boul[R_OUT*DD];
__device__ __align__(1024) __nv_bfloat16 g_Bovh[DD*R_OUT],  g_Bovl[DD*R_OUT];
__device__ __align__(1024) __nv_bfloat16 g_Bf1uh[R_FC*DD],  g_Bf1ul[R_FC*DD];
__device__ __align__(1024) __nv_bfloat16 g_Bf1vh[II*R_FC],  g_Bf1vl[II*R_FC];
__device__ __align__(1024) __nv_bfloat16 g_Bf2uh[R_FC*II],  g_Bf2ul[R_FC*II];
__device__ __align__(1024) __nv_bfloat16 g_Bf2vh[DD*R_FC],  g_Bf2vl[DD*R_FC];

// ================= low-level helpers (baseline PTX, sm_80+) =================
__device__ __forceinline__ uint32_t smem_u32(const void* p) {
    uint32_t a;
    asm("{ .reg .u64 t; cvta.to.shared.u64 t, %1; cvt.u32.u64 %0, t; }" : "=r"(a) : "l"(p));
    return a;
}
__device__ __forceinline__ void cpa16(uint32_t dst, const void* src) {
    asm volatile("cp.async.cg.shared.global [%0], [%1], 16;" :: "r"(dst), "l"(src) : "memory");
}
#define CP_COMMIT() asm volatile("cp.async.commit_group;" ::: "memory")
#define CP_WAIT(n)  asm volatile("cp.async.wait_group %0;" :: "n"(n) : "memory")

__device__ __forceinline__ uint32_t lds32(uint32_t a) {
    uint32_t v;
    asm("ld.shared.b32 %0, [%1];" : "=r"(v) : "r"(a));
    return v;
}
__device__ __forceinline__ void mma16816(float* c, uint32_t a0, uint32_t a1, uint32_t a2,
                                         uint32_t a3, uint32_t b0, uint32_t b1) {
    asm volatile(
        "mma.sync.aligned.m16n8k16.row.col.f32.bf16.bf16.f32 "
        "{%0,%1,%2,%3}, {%4,%5,%6,%7}, {%8,%9}, {%0,%1,%2,%3};"
        : "+f"(c[0]), "+f"(c[1]), "+f"(c[2]), "+f"(c[3])
        : "r"(a0), "r"(a1), "r"(a2), "r"(a3), "r"(b0), "r"(b1));
}

// ---------------- split conversions ----------------
__global__ void convA(const float* __restrict__ in, __nv_bfloat16* __restrict__ hi,
                      __nv_bfloat16* __restrict__ lo) {
    int i = blockIdx.x * 256 + threadIdx.x;
    float4 v = ((const float4*)in)[i];
    __nv_bfloat16 h0 = __float2bfloat16(v.x), h1 = __float2bfloat16(v.y);
    __nv_bfloat16 h2 = __float2bfloat16(v.z), h3 = __float2bfloat16(v.w);
    __nv_bfloat16 l0 = __float2bfloat16(v.x - __bfloat162float(h0));
    __nv_bfloat16 l1 = __float2bfloat16(v.y - __bfloat162float(h1));
    __nv_bfloat16 l2 = __float2bfloat16(v.z - __bfloat162float(h2));
    __nv_bfloat16 l3 = __float2bfloat16(v.w - __bfloat162float(h3));
    __nv_bfloat162 p0; p0.x = h0; p0.y = h1;
    __nv_bfloat162 p1; p1.x = h2; p1.y = h3;
    __nv_bfloat162 q0; q0.x = l0; q0.y = l1;
    __nv_bfloat162 q1; q1.x = l2; q1.y = l3;
    ((__nv_bfloat162*)hi)[2*i]   = p0;
    ((__nv_bfloat162*)hi)[2*i+1] = p1;
    ((__nv_bfloat162*)lo)[2*i]   = q0;
    ((__nv_bfloat162*)lo)[2*i+1] = q1;
}

// W[K,N] fp32 -> W^T [N,K] bf16 hi/lo (tiled transpose)
__global__ void convW(const float* __restrict__ W, __nv_bfloat16* __restrict__ hi,
                      __nv_bfloat16* __restrict__ lo, int K, int N) {
    __shared__ float t[32][33];
    int n0 = blockIdx.x * 32, k0 = blockIdx.y * 32;
    int tx = threadIdx.x, ty = threadIdx.y;  // 32x8
    #pragma unroll
    for (int i = 0; i < 4; i++)
        t[ty + 8*i][tx] = W[(size_t)(k0 + ty + 8*i) * N + n0 + tx];
    __syncthreads();
    #pragma unroll
    for (int i = 0; i < 4; i++) {
        float v = t[tx][ty + 8*i];
        __nv_bfloat16 h = __float2bfloat16(v);
        __nv_bfloat16 l = __float2bfloat16(v - __bfloat162float(h));
        size_t o = (size_t)(n0 + ty + 8*i) * K + k0 + tx;
        hi[o] = h; lo[o] = l;
    }
}

// ---------------- mma.sync GEMM: C[M,N] = (Ah+Al)[M,K] @ (Bh+Bl)[N,K]^T -----
// 128x128 CTA tile, BK=32, 8 warps (2x4), warp tile 64x32, cp.async 2-stage.
// smem per matrix per stage: 128 rows x 40 bf16 (pad) = 10240 B; 4 matrices.
// EPI: 0 = none, 1 = bias+residual, 2 = bias+exact GELU
#define PAD_W 40
#define MAT_B (128*PAD_W*2)   // 10240
#define STG_B (4*MAT_B)       // 40960
#define GM_SMEM (2*STG_B)     // 81920

__device__ __forceinline__ void copy_stage(uint32_t sst,
        const __nv_bfloat16* __restrict__ Ahp, const __nv_bfloat16* __restrict__ Alp,
        const __nv_bfloat16* __restrict__ Bhp, const __nv_bfloat16* __restrict__ Blp,
        int K, int k0, int tid) {
    #pragma unroll
    for (int it = 0; it < 2; it++) {
        int i = tid + it * 256;
        int row = i >> 2, q = i & 3;
        size_t go = (size_t)row * K + k0 + q * 8;
        uint32_t so = (uint32_t)(row * PAD_W + q * 8) * 2;
        cpa16(sst + so,             Ahp + go);
        cpa16(sst + MAT_B + so,     Alp + go);
        cpa16(sst + 2*MAT_B + so,   Bhp + go);
        cpa16(sst + 3*MAT_B + so,   Blp + go);
    }
}

template<int EPI>
__global__ void __launch_bounds__(256, 2)
gemm_mma(const __nv_bfloat16* __restrict__ Ah, const __nv_bfloat16* __restrict__ Al,
         const __nv_bfloat16* __restrict__ Bh, const __nv_bfloat16* __restrict__ Bl,
         float* __restrict__ C, const float* __restrict__ bias,
         const float* __restrict__ res, int M, int N, int K) {
    extern __shared__ char smem_raw[];
    uint32_t sbase = smem_u32(smem_raw);
    int tid = threadIdx.x;
    int wid = tid >> 5, lane = tid & 31;
    int wm = wid >> 2;          // 0..1
    int wn = wid & 3;           // 0..3
    int g  = lane >> 2;         // 0..7
    int i4 = lane & 3;          // 0..3
    int bm = blockIdx.y * 128, bn = blockIdx.x * 128;

    const __nv_bfloat16* Ahp = Ah + (size_t)bm * K;
    const __nv_bfloat16* Alp = Al + (size_t)bm * K;
    const __nv_bfloat16* Bhp = Bh + (size_t)bn * K;
    const __nv_bfloat16* Blp = Bl + (size_t)bn * K;

    float acc[4][4][4];
    #pragma unroll
    for (int a = 0; a < 4; a++)
        #pragma unroll
        for (int b = 0; b < 4; b++)
            #pragma unroll
            for (int c = 0; c < 4; c++) acc[a][b][c] = 0.f;

    int NC = K >> 5;
    copy_stage(sbase, Ahp, Alp, Bhp, Blp, K, 0, tid);
    CP_COMMIT();

    for (int c = 0; c < NC; c++) {
        if (c + 1 < NC) {
            copy_stage(sbase + ((c + 1) & 1) * STG_B, Ahp, Alp, Bhp, Blp,
                       K, (c + 1) << 5, tid);
            CP_COMMIT();
            CP_WAIT(1);
        } else {
            CP_WAIT(0);
        }
        __syncthreads();

        uint32_t st = sbase + (c & 1) * STG_B;
        uint32_t stAh = st, stAl = st + MAT_B, stBh = st + 2*MAT_B, stBl = st + 3*MAT_B;

        #pragma unroll
        for (int ks = 0; ks < 2; ks++) {
            uint32_t bh[4][2], bl[4][2];
            #pragma unroll
            for (int ni = 0; ni < 4; ni++) {
                uint32_t off = (uint32_t)(((wn * 32 + ni * 8 + g) * PAD_W) / 2 + i4 + ks * 8) * 4;
                bh[ni][0] = lds32(stBh + off);
                bh[ni][1] = lds32(stBh + off + 16);
                bl[ni][0] = lds32(stBl + off);
                bl[ni][1] = lds32(stBl + off + 16);
            }
            #pragma unroll
            for (int mi = 0; mi < 4; mi++) {
                uint32_t off = (uint32_t)(((wm * 64 + mi * 16 + g) * PAD_W) / 2 + i4 + ks * 8) * 4;
                uint32_t ah0 = lds32(stAh + off);
                uint32_t ah1 = lds32(stAh + off + 640);
                uint32_t ah2 = lds32(stAh + off + 16);
                uint32_t ah3 = lds32(stAh + off + 656);
                uint32_t al0 = lds32(stAl + off);
                uint32_t al1 = lds32(stAl + off + 640);
                uint32_t al2 = lds32(stAl + off + 16);
                uint32_t al3 = lds32(stAl + off + 656);
                #pragma unroll
                for (int ni = 0; ni < 4; ni++) {
                    mma16816(acc[mi][ni], ah0, ah1, ah2, ah3, bh[ni][0], bh[ni][1]);
                    mma16816(acc[mi][ni], ah0, ah1, ah2, ah3, bl[ni][0], bl[ni][1]);
                    mma16816(acc[mi][ni], al0, al1, al2, al3, bh[ni][0], bh[ni][1]);
                }
            }
        }
        __syncthreads();
    }

    // epilogue
    #pragma unroll
    for (int mi = 0; mi < 4; mi++) {
        int row0 = bm + wm * 64 + mi * 16 + g;
        #pragma unroll
        for (int ni = 0; ni < 4; ni++) {
            int col = bn + wn * 32 + ni * 8 + i4 * 2;
            float v[4];
            v[0] = acc[mi][ni][0]; v[1] = acc[mi][ni][1];
            v[2] = acc[mi][ni][2]; v[3] = acc[mi][ni][3];
            if (EPI != 0) {
                float b0 = bias[col], b1 = bias[col + 1];
                v[0] += b0; v[1] += b1; v[2] += b0; v[3] += b1;
            }
            if (EPI == 2) {
                #pragma unroll
                for (int t = 0; t < 4; t++)
                    v[t] = 0.5f * v[t] * (1.0f + erff(v[t] * 0.70710678118654752f));
            }
            float* p0 = C + (size_t)row0 * N + col;
            float* p1 = p0 + 8 * (size_t)N;
            if (EPI == 1) {
                const float* r0 = res + (size_t)row0 * N + col;
                const float* r1 = r0 + 8 * (size_t)N;
                v[0] += r0[0]; v[1] += r0[1]; v[2] += r1[0]; v[3] += r1[1];
            }
            *(float2*)p0 = make_float2(v[0], v[1]);
            *(float2*)p1 = make_float2(v[2], v[3]);
        }
    }
}

// ---------------- layernorm: one block per row, 256 threads ----------------
__global__ void ln_kernel(const float* __restrict__ in, float* __restrict__ out,
                          const float* __restrict__ gw, const float* __restrict__ bw) {
    int row = blockIdx.x;
    int tid = threadIdx.x;
    const float4* x4 = (const float4*)(in + (size_t)row * DD);
    float4 v = x4[tid];
    __shared__ float red[8];
    __shared__ float stat[2];
    float s = v.x + v.y + v.z + v.w;
    #pragma unroll
    for (int o = 16; o; o >>= 1) s += __shfl_xor_sync(0xffffffffu, s, o);
    if ((tid & 31) == 0) red[tid >> 5] = s;
    __syncthreads();
    if (tid < 32) {
        float t = (tid < 8) ? red[tid] : 0.f;
        #pragma unroll
        for (int o = 4; o; o >>= 1) t += __shfl_xor_sync(0xffffffffu, t, o);
        if (tid == 0) stat[0] = t * (1.0f / DD);
    }
    __syncthreads();
    float mu = stat[0];
    float a = v.x - mu, b = v.y - mu, c = v.z - mu, d = v.w - mu;
    float s2 = a*a + b*b + c*c + d*d;
    #pragma unroll
    for (int o = 16; o; o >>= 1) s2 += __shfl_xor_sync(0xffffffffu, s2, o);
    if ((tid & 31) == 0) red[tid >> 5] = s2;
    __syncthreads();
    if (tid < 32) {
        float t = (tid < 8) ? red[tid] : 0.f;
        #pragma unroll
        for (int o = 4; o; o >>= 1) t += __shfl_xor_sync(0xffffffffu, t, o);
        if (tid == 0) stat[1] = rsqrtf(t * (1.0f / DD) + 1e-5f);
    }
    __syncthreads();
    float rs = stat[1];
    float4 g4 = ((const float4*)gw)[tid];
    float4 b4 = ((const float4*)bw)[tid];
    float4 o4 = make_float4(a*rs*g4.x + b4.x, b*rs*g4.y + b4.y,
                            c*rs*g4.z + b4.z, d*rs*g4.w + b4.w);
    ((float4*)(out + (size_t)row * DD))[tid] = o4;
}

// ---------------- per-head rank expansion: [*,32]@[32,64]+bias -> [B,H,S,DH]
__global__ void expand_heads(const float* __restrict__ Xr, const float* __restrict__ Vh,
                             const float* __restrict__ bias, float* __restrict__ out, int ld) {
    int bh = blockIdx.y;
    int b  = bh / HH;
    int h  = bh % HH;
    int s0 = blockIdx.x * 64;
    __shared__ float Vs[RA][DHD];
    __shared__ float Xs[64][RA];
    int tid = threadIdx.x;
    const float* vp = Vh + (size_t)h * RA * DHD;
    for (int i = tid; i < RA * DHD / 4; i += 256)
        ((float4*)Vs)[i] = ((const float4*)vp)[i];
    for (int i = tid; i < 64 * RA / 4; i += 256) {
        int r = i >> 3, c4 = (i & 7) << 2;
        *(float4*)&Xs[r][c4] =
            *(const float4*)(Xr + (size_t)(b * SS + s0 + r) * ld + h * RA + c4);
    }
    __syncthreads();
    for (int i = tid; i < 64 * DHD; i += 256) {
        int sl = i >> 6, e = i & 63;
        float acc = bias[h * DHD + e];
        #pragma unroll
        for (int r = 0; r < RA; r++) acc = fmaf(Xs[sl][r], Vs[r][e], acc);
        out[((size_t)bh * SS + s0 + sl) * DHD + e] = acc;
    }
}

// ---------------- flash attention (causal), 64x64 tiles, DH=64, fp32 --------
#define FLD 68
__global__ void __launch_bounds__(256, 2)
flash_attn(const float* __restrict__ Q, const float* __restrict__ K,
           const float* __restrict__ V, float* __restrict__ O) {
    extern __shared__ float sm[];
    float* Qs = sm;
    float* Ks = Qs + 64 * FLD;
    float* Vs = Ks + 64 * FLD;
    float* Ps = Vs + 64 * FLD;
    int bh = blockIdx.y;
    int m0 = (gridDim.x - 1 - blockIdx.x) * 64;
    const float* Qg = Q + ((size_t)bh * SS + m0) * DHD;
    const float* Kg = K + (size_t)bh * SS * DHD;
    const float* Vg = V + (size_t)bh * SS * DHD;
    int tid = threadIdx.x;
    int tr = tid >> 4, tc = tid & 15;

    for (int i = tid; i < 1024; i += 256) {
        int r = i >> 4, c4 = (i & 15) << 2;
        *(float4*)(Qs + r * FLD + c4) = *(const float4*)(Qg + (size_t)r * DHD + c4);
    }
    float o[4][4];
    float m_i[4], l_i[4];
    #pragma unroll
    for (int i = 0; i < 4; i++) {
        m_i[i] = -1e30f; l_i[i] = 0.f;
        #pragma unroll
        for (int j = 0; j < 4; j++) o[i][j] = 0.f;
    }

    for (int n0 = 0; n0 <= m0; n0 += 64) {
        __syncthreads();
        for (int i = tid; i < 1024; i += 256) {
            int r = i >> 4, c4 = (i & 15) << 2;
            *(float4*)(Ks + r * FLD + c4) = *(const float4*)(Kg + (size_t)(n0 + r) * DHD + c4);
            *(float4*)(Vs + r * FLD + c4) = *(const float4*)(Vg + (size_t)(n0 + r) * DHD + c4);
        }
        __syncthreads();

        float s[4][4];
        #pragma unroll
        for (int i = 0; i < 4; i++)
            #pragma unroll
            for (int j = 0; j < 4; j++) s[i][j] = 0.f;
        #pragma unroll 8
        for (int k = 0; k < 64; k++) {
            float qf[4], kf[4];
            #pragma unroll
            for (int i = 0; i < 4; i++) qf[i] = Qs[(tr * 4 + i) * FLD + k];
            #pragma unroll
            for (int j = 0; j < 4; j++) kf[j] = Ks[(tc * 4 + j) * FLD + k];
            #pragma unroll
            for (int i = 0; i < 4; i++)
                #pragma unroll
                for (int j = 0; j < 4; j++) s[i][j] = fmaf(qf[i], kf[j], s[i][j]);
        }
        const float scale = 0.125f;
        bool diag = (n0 == m0);
        float pr[4][4], alpha[4];
        #pragma unroll
        for (int i = 0; i < 4; i++) {
            int grow = tr * 4 + i;
            float mx = -1e30f;
            #pragma unroll
            for (int j = 0; j < 4; j++) {
                float v = s[i][j] * scale;
                if (diag && (tc * 4 + j) > grow) v = -1e30f;
                s[i][j] = v;
                mx = fmaxf(mx, v);
            }
            #pragma unroll
            for (int off = 8; off; off >>= 1)
                mx = fmaxf(mx, __shfl_xor_sync(0xffffffffu, mx, off));
            float newm = fmaxf(m_i[i], mx);
            float a = __expf(m_i[i] - newm);
            float rs = 0.f;
            #pragma unroll
            for (int j = 0; j < 4; j++) {
                float p = __expf(s[i][j] - newm);
                pr[i][j] = p; rs += p;
            }
            #pragma unroll
            for (int off = 8; off; off >>= 1)
                rs += __shfl_xor_sync(0xffffffffu, rs, off);
            l_i[i] = l_i[i] * a + rs;
            m_i[i] = newm;
            alpha[i] = a;
        }
        #pragma unroll
        for (int i = 0; i < 4; i++)
            #pragma unroll
            for (int j = 0; j < 4; j++) o[i][j] *= alpha[i];
        #pragma unroll
        for (int i = 0; i < 4; i++)
            #pragma unroll
            for (int j = 0; j < 4; j++)
                Ps[(tr * 4 + i) * FLD + tc * 4 + j] = pr[i][j];
        __syncthreads();
        #pragma unroll 8
        for (int n = 0; n < 64; n++) {
            float pv[4], vv[4];
            #pragma unroll
            for (int i = 0; i < 4; i++) pv[i] = Ps[(tr * 4 + i) * FLD + n];
            #pragma unroll
            for (int j = 0; j < 4; j++) vv[j] = Vs[n * FLD + tc * 4 + j];
            #pragma unroll
            for (int i = 0; i < 4; i++)
                #pragma unroll
                for (int j = 0; j < 4; j++) o[i][j] = fmaf(pv[i], vv[j], o[i][j]);
        }
    }

    float* Og = O + ((size_t)bh * SS + m0) * DHD;
    #pragma unroll
    for (int i = 0; i < 4; i++) {
        float inv = 1.0f / l_i[i];
        #pragma unroll
        for (int j = 0; j < 4; j++)
            Og[(size_t)(tr * 4 + i) * DHD + tc * 4 + j] = o[i][j] * inv;
    }
}

// ---------------- merge heads ----------------
__global__ void merge_heads(const float* __restrict__ Yh, float* __restrict__ Y) {
    size_t idx = (size_t)blockIdx.x * 256 + threadIdx.x;
    size_t row = idx >> 8;
    int c4 = (int)(idx & 255) << 2;
    int b_ = (int)(row >> 11);
    int s_ = (int)(row & 2047);
    int h_ = c4 >> 6;
    int e  = c4 & 63;
    float4 v = *(const float4*)(Yh + (((size_t)(b_ * HH + h_) * SS + s_) * DHD + e));
    *(float4*)(Y + row * DD + c4) = v;
}

// ---------------- host launcher ----------------
extern "C" void kernel_launch(void* const* d_in, const int* in_sizes, int n_in,
                              void* d_out, int out_size) {
    const float* hidden = (const float*)d_in[0];
    const float* ln1_g  = (const float*)d_in[1];
    const float* ln1_b  = (const float*)d_in[2];
    const float* ln2_g  = (const float*)d_in[3];
    const float* ln2_b  = (const float*)d_in[4];
    const float* q_U = (const float*)d_in[5];
    const float* q_V = (const float*)d_in[6];
    const float* q_b = (const float*)d_in[7];
    const float* k_U = (const float*)d_in[8];
    const float* k_V = (const float*)d_in[9];
    const float* k_b = (const float*)d_in[10];
    const float* v_U = (const float*)d_in[11];
    const float* v_V = (const float*)d_in[12];
    const float* v_b = (const float*)d_in[13];
    const float* out_U = (const float*)d_in[14];
    const float* out_V = (const float*)d_in[15];
    const float* out_b = (const float*)d_in[16];
    const float* fc1_U = (const float*)d_in[17];
    const float* fc1_V = (const float*)d_in[18];
    const float* fc1_b = (const float*)d_in[19];
    const float* fc2_U = (const float*)d_in[20];
    const float* fc2_V = (const float*)d_in[21];
    const float* fc2_b = (const float*)d_in[22];
    float* out = (float*)d_out;

    float *x, *QKVr, *Qb, *Kb, *Vb, *Yh, *Y, *T1, *hb, *z, *T2, *H1, *T3;
    __nv_bfloat16 *Ah, *Al, *Bqkvh, *Bqkvl, *Bouh, *Boul, *Bovh, *Bovl;
    __nv_bfloat16 *Bf1uh, *Bf1ul, *Bf1vh, *Bf1vl, *Bf2uh, *Bf2ul, *Bf2vh, *Bf2vl;
    cudaGetSymbolAddress((void**)&x,    g_x);
    cudaGetSymbolAddress((void**)&QKVr, g_QKVr);
    cudaGetSymbolAddress((void**)&Qb,   g_Q);
    cudaGetSymbolAddress((void**)&Kb,   g_K);
    cudaGetSymbolAddress((void**)&Vb,   g_V);
    cudaGetSymbolAddress((void**)&Yh,   g_Yh);
    cudaGetSymbolAddress((void**)&Y,    g_Y);
    cudaGetSymbolAddress((void**)&T1,   g_T1);
    cudaGetSymbolAddress((void**)&hb,   g_h);
    cudaGetSymbolAddress((void**)&z,    g_z);
    cudaGetSymbolAddress((void**)&T2,   g_T2);
    cudaGetSymbolAddress((void**)&H1,   g_H1);
    cudaGetSymbolAddress((void**)&T3,   g_T3);
    cudaGetSymbolAddress((void**)&Ah,   g_Ah);
    cudaGetSymbolAddress((void**)&Al,   g_Al);
    cudaGetSymbolAddress((void**)&Bqkvh, g_Bqkvh);
    cudaGetSymbolAddress((void**)&Bqkvl, g_Bqkvl);
    cudaGetSymbolAddress((void**)&Bouh, g_Bouh);
    cudaGetSymbolAddress((void**)&Boul, g_Boul);
    cudaGetSymbolAddress((void**)&Bovh, g_Bovh);
    cudaGetSymbolAddress((void**)&Bovl, g_Bovl);
    cudaGetSymbolAddress((void**)&Bf1uh, g_Bf1uh);
    cudaGetSymbolAddress((void**)&Bf1ul, g_Bf1ul);
    cudaGetSymbolAddress((void**)&Bf1vh, g_Bf1vh);
    cudaGetSymbolAddress((void**)&Bf1vl, g_Bf1vl);
    cudaGetSymbolAddress((void**)&Bf2uh, g_Bf2uh);
    cudaGetSymbolAddress((void**)&Bf2ul, g_Bf2ul);
    cudaGetSymbolAddress((void**)&Bf2vh, g_Bf2vh);
    cudaGetSymbolAddress((void**)&Bf2vl, g_Bf2vl);

    cudaFuncSetAttribute(gemm_mma<0>, cudaFuncAttributeMaxDynamicSharedMemorySize, GM_SMEM);
    cudaFuncSetAttribute(gemm_mma<1>, cudaFuncAttributeMaxDynamicSharedMemorySize, GM_SMEM);
    cudaFuncSetAttribute(gemm_mma<2>, cudaFuncAttributeMaxDynamicSharedMemorySize, GM_SMEM);
    int fa_smem = 4 * 64 * FLD * sizeof(float);
    cudaFuncSetAttribute(flash_attn, cudaFuncAttributeMaxDynamicSharedMemorySize, fa_smem);

    dim3 wblk(32, 8);
    // --- weight conversions ---
    convW<<<dim3(HR/32, DD/32), wblk>>>(q_U, Bqkvh,            Bqkvl,            DD, HR);
    convW<<<dim3(HR/32, DD/32), wblk>>>(k_U, Bqkvh + HR*DD,    Bqkvl + HR*DD,    DD, HR);
    convW<<<dim3(HR/32, DD/32), wblk>>>(v_U, Bqkvh + 2*HR*DD,  Bqkvl + 2*HR*DD,  DD, HR);
    convW<<<dim3(R_OUT/32, DD/32), wblk>>>(out_U, Bouh, Boul, DD, R_OUT);
    convW<<<dim3(DD/32, R_OUT/32), wblk>>>(out_V, Bovh, Bovl, R_OUT, DD);
    convW<<<dim3(R_FC/32, DD/32), wblk>>>(fc1_U, Bf1uh, Bf1ul, DD, R_FC);
    convW<<<dim3(II/32, R_FC/32), wblk>>>(fc1_V, Bf1vh, Bf1vl, R_FC, II);
    convW<<<dim3(R_FC/32, II/32), wblk>>>(fc2_U, Bf2uh, Bf2ul, II, R_FC);
    convW<<<dim3(DD/32, R_FC/32), wblk>>>(fc2_V, Bf2vh, Bf2vl, R_FC, DD);

    // 1. LN1 + split
    ln_kernel<<<NROW, 256>>>(hidden, x, ln1_g, ln1_b);
    convA<<<(NROW*DD/4)/256, 256>>>(x, Ah, Al);
    // 2. fused qkv rank projection -> [4096, 1536]
    gemm_mma<0><<<dim3(HR3/128, NROW/128), 256, GM_SMEM>>>(Ah, Al, Bqkvh, Bqkvl, QKVr,
                                                           nullptr, nullptr, NROW, HR3, DD);
    // 3. per-head expansion
    expand_heads<<<dim3(SS/64, BB*HH), 256>>>(QKVr,        q_V, q_b, Qb, HR3);
    expand_heads<<<dim3(SS/64, BB*HH), 256>>>(QKVr + HR,   k_V, k_b, Kb, HR3);
    expand_heads<<<dim3(SS/64, BB*HH), 256>>>(QKVr + 2*HR, v_V, v_b, Vb, HR3);
    // 4. causal flash attention
    flash_attn<<<dim3(SS/64, BB*HH), 256, fa_smem>>>(Qb, Kb, Vb, Yh);
    // 5. merge heads
    merge_heads<<<(NROW*DD/4)/256, 256>>>(Yh, Y);
    // 6. out projection + residual
    convA<<<(NROW*DD/4)/256, 256>>>(Y, Ah, Al);
    gemm_mma<0><<<dim3(R_OUT/128, NROW/128), 256, GM_SMEM>>>(Ah, Al, Bouh, Boul, T1,
                                                             nullptr, nullptr, NROW, R_OUT, DD);
    convA<<<(NROW*R_OUT/4)/256, 256>>>(T1, Ah, Al);
    gemm_mma<1><<<dim3(DD/128, NROW/128), 256, GM_SMEM>>>(Ah, Al, Bovh, Bovl, hb,
                                                          out_b, hidden, NROW, DD, R_OUT);
    // 7. LN2
    ln_kernel<<<NROW, 256>>>(hb, z, ln2_g, ln2_b);
    // 8. MLP
    convA<<<(NROW*DD/4)/256, 256>>>(z, Ah, Al);
    gemm_mma<0><<<dim3(R_FC/128, NROW/128), 256, GM_SMEM>>>(Ah, Al, Bf1uh, Bf1ul, T2,
                                                            nullptr, nullptr, NROW, R_FC, DD);
    convA<<<(NROW*R_FC/4)/256, 256>>>(T2, Ah, Al);
    gemm_mma<2><<<dim3(II/128, NROW/128), 256, GM_SMEM>>>(Ah, Al, Bf1vh, Bf1vl, H1,
                                                          fc1_b, nullptr, NROW, II, R_FC);
    convA<<<(NROW*II/4)/256, 256>>>(H1, Ah, Al);
    gemm_mma<0><<<dim3(R_FC/128, NROW/128), 256, GM_SMEM>>>(Ah, Al, Bf2uh, Bf2ul, T3,
                                                            nullptr, nullptr, NROW, R_FC, II);
    convA<<<(NROW*R_FC/4)/256, 256>>>(T3, Ah, Al);
    gemm_mma<1><<<dim3(DD/128, NROW/128), 256, GM_SMEM>>>(Ah, Al, Bf2vh, Bf2vl, out,
                                                          fc2_b, hb, NROW, DD, R_FC);
}

// round 4
// speedup vs baseline: 3.7117x; 2.1203x over previous
#include <cuda_runtime.h>
#include <cuda_bf16.h>
#include <math.h>
#include <stdint.h>

// ---------------- problem constants ----------------
#define BB 2
#define SS 2048
#define DD 1024
#define HH 16
#define DHD 64
#define NROW (BB*SS)      // 4096
#define RA 32
#define HR 512
#define HR3 1536
#define R_OUT 512
#define II 4096
#define R_FC 512

// ---------------- device scratch ----------------
__device__ float g_QKVr[NROW*HR3];
__device__ float g_h   [NROW*DD];

__device__ __align__(1024) __nv_bfloat16 g_Qbf[NROW*DD];
__device__ __align__(1024) __nv_bfloat16 g_Kbf[NROW*DD];
__device__ __align__(1024) __nv_bfloat16 g_Vbf[NROW*DD];

// split ping-pong activation buffers
__device__ __align__(1024) __nv_bfloat16 g_Ah[NROW*II];
__device__ __align__(1024) __nv_bfloat16 g_Al[NROW*II];
__device__ __align__(1024) __nv_bfloat16 g_Ch[NROW*II];
__device__ __align__(1024) __nv_bfloat16 g_Cl[NROW*II];

// split weights (transposed to [N,K])
__device__ __align__(1024) __nv_bfloat16 g_Bqkvh[HR3*DD], g_Bqkvl[HR3*DD];
__device__ __align__(1024) __nv_bfloat16 g_Bouh[R_OUT*DD],  g_Boul[R_OUT*DD];
__device__ __align__(1024) __nv_bfloat16 g_Bovh[DD*R_OUT],  g_Bovl[DD*R_OUT];
__device__ __align__(1024) __nv_bfloat16 g_Bf1uh[R_FC*DD],  g_Bf1ul[R_FC*DD];
__device__ __align__(1024) __nv_bfloat16 g_Bf1vh[II*R_FC],  g_Bf1vl[II*R_FC];
__device__ __align__(1024) __nv_bfloat16 g_Bf2uh[R_FC*II],  g_Bf2ul[R_FC*II];
__device__ __align__(1024) __nv_bfloat16 g_Bf2vh[DD*R_FC],  g_Bf2vl[DD*R_FC];

// ================= low-level helpers =================
__device__ __forceinline__ uint32_t smem_u32(const void* p) {
    uint32_t a;
    asm("{ .reg .u64 t; cvta.to.shared.u64 t, %1; cvt.u32.u64 %0, t; }" : "=r"(a) : "l"(p));
    return a;
}
__device__ __forceinline__ void cpa16(uint32_t dst, const void* src) {
    asm volatile("cp.async.cg.shared.global [%0], [%1], 16;" :: "r"(dst), "l"(src) : "memory");
}
#define CP_COMMIT() asm volatile("cp.async.commit_group;" ::: "memory")
#define CP_WAIT(n)  asm volatile("cp.async.wait_group %0;" :: "n"(n) : "memory")

__device__ __forceinline__ uint32_t lds32(uint32_t a) {
    uint32_t v;
    asm("ld.shared.b32 %0, [%1];" : "=r"(v) : "r"(a));
    return v;
}
__device__ __forceinline__ void mma16816(float* c, uint32_t a0, uint32_t a1, uint32_t a2,
                                         uint32_t a3, uint32_t b0, uint32_t b1) {
    asm volatile(
        "mma.sync.aligned.m16n8k16.row.col.f32.bf16.bf16.f32 "
        "{%0,%1,%2,%3}, {%4,%5,%6,%7}, {%8,%9}, {%0,%1,%2,%3};"
        : "+f"(c[0]), "+f"(c[1]), "+f"(c[2]), "+f"(c[3])
        : "r"(a0), "r"(a1), "r"(a2), "r"(a3), "r"(b0), "r"(b1));
}
__device__ __forceinline__ void ldmx4t(uint32_t& r0, uint32_t& r1, uint32_t& r2,
                                       uint32_t& r3, uint32_t addr) {
    asm volatile("ldmatrix.sync.aligned.m8n8.x4.trans.shared.b16 {%0,%1,%2,%3}, [%4];"
                 : "=r"(r0), "=r"(r1), "=r"(r2), "=r"(r3) : "r"(addr));
}
__device__ __forceinline__ uint32_t packbf(float a, float b) {
    __nv_bfloat162 t = __float22bfloat162_rn(make_float2(a, b));
    return *(uint32_t*)&t;
}
__device__ __forceinline__ void split_pair(float v0, float v1, uint32_t& hi, uint32_t& lo) {
    __nv_bfloat16 h0 = __float2bfloat16(v0), h1 = __float2bfloat16(v1);
    __nv_bfloat16 l0 = __float2bfloat16(v0 - __bfloat162float(h0));
    __nv_bfloat16 l1 = __float2bfloat16(v1 - __bfloat162float(h1));
    __nv_bfloat162 H; H.x = h0; H.y = h1;
    __nv_bfloat162 L; L.x = l0; L.y = l1;
    hi = *(uint32_t*)&H; lo = *(uint32_t*)&L;
}

// ---------------- weight transpose + split ----------------
__global__ void convW(const float* __restrict__ W, __nv_bfloat16* __restrict__ hi,
                      __nv_bfloat16* __restrict__ lo, int K, int N) {
    __shared__ float t[32][33];
    int n0 = blockIdx.x * 32, k0 = blockIdx.y * 32;
    int tx = threadIdx.x, ty = threadIdx.y;
    #pragma unroll
    for (int i = 0; i < 4; i++)
        t[ty + 8*i][tx] = W[(size_t)(k0 + ty + 8*i) * N + n0 + tx];
    __syncthreads();
    #pragma unroll
    for (int i = 0; i < 4; i++) {
        float v = t[tx][ty + 8*i];
        __nv_bfloat16 h = __float2bfloat16(v);
        __nv_bfloat16 l = __float2bfloat16(v - __bfloat162float(h));
        size_t o = (size_t)(n0 + ty + 8*i) * K + k0 + tx;
        hi[o] = h; lo[o] = l;
    }
}

// ---------------- mma.sync GEMM (3-pass hi/lo) ----------------
// EPI: 0=none, 1=bias+residual, 2=bias+GELU ; OUT: 0=fp32 C, 1=bf16 hi/lo split
#define PAD_W 40
#define MAT_B (128*PAD_W*2)
#define STG_B (4*MAT_B)
#define GM_SMEM (2*STG_B)

__device__ __forceinline__ void copy_stage(uint32_t sst,
        const __nv_bfloat16* __restrict__ Ahp, const __nv_bfloat16* __restrict__ Alp,
        const __nv_bfloat16* __restrict__ Bhp, const __nv_bfloat16* __restrict__ Blp,
        int K, int k0, int tid) {
    #pragma unroll
    for (int it = 0; it < 2; it++) {
        int i = tid + it * 256;
        int row = i >> 2, q = i & 3;
        size_t go = (size_t)row * K + k0 + q * 8;
        uint32_t so = (uint32_t)(row * PAD_W + q * 8) * 2;
        cpa16(sst + so,           Ahp + go);
        cpa16(sst + MAT_B + so,   Alp + go);
        cpa16(sst + 2*MAT_B + so, Bhp + go);
        cpa16(sst + 3*MAT_B + so, Blp + go);
    }
}

template<int EPI, int OUT>
__global__ void __launch_bounds__(256, 2)
gemm_mma(const __nv_bfloat16* __restrict__ Ah, const __nv_bfloat16* __restrict__ Al,
         const __nv_bfloat16* __restrict__ Bh, const __nv_bfloat16* __restrict__ Bl,
         float* __restrict__ C, __nv_bfloat16* __restrict__ Oh, __nv_bfloat16* __restrict__ Ol,
         const float* __restrict__ bias, const float* __restrict__ res,
         int M, int N, int K) {
    extern __shared__ char smem_raw[];
    uint32_t sbase = smem_u32(smem_raw);
    int tid = threadIdx.x;
    int wid = tid >> 5, lane = tid & 31;
    int wm = wid >> 2, wn = wid & 3;
    int g = lane >> 2, i4 = lane & 3;
    int bm = blockIdx.y * 128, bn = blockIdx.x * 128;

    const __nv_bfloat16* Ahp = Ah + (size_t)bm * K;
    const __nv_bfloat16* Alp = Al + (size_t)bm * K;
    const __nv_bfloat16* Bhp = Bh + (size_t)bn * K;
    const __nv_bfloat16* Blp = Bl + (size_t)bn * K;

    float acc[4][4][4];
    #pragma unroll
    for (int a = 0; a < 4; a++)
        #pragma unroll
        for (int b = 0; b < 4; b++)
            #pragma unroll
            for (int c = 0; c < 4; c++) acc[a][b][c] = 0.f;

    int NC = K >> 5;
    copy_stage(sbase, Ahp, Alp, Bhp, Blp, K, 0, tid);
    CP_COMMIT();

    for (int c = 0; c < NC; c++) {
        if (c + 1 < NC) {
            copy_stage(sbase + ((c + 1) & 1) * STG_B, Ahp, Alp, Bhp, Blp,
                       K, (c + 1) << 5, tid);
            CP_COMMIT();
            CP_WAIT(1);
        } else {
            CP_WAIT(0);
        }
        __syncthreads();

        uint32_t st = sbase + (c & 1) * STG_B;
        uint32_t stAh = st, stAl = st + MAT_B, stBh = st + 2*MAT_B, stBl = st + 3*MAT_B;

        #pragma unroll
        for (int ks = 0; ks < 2; ks++) {
            uint32_t bh[4][2], bl[4][2];
            #pragma unroll
            for (int ni = 0; ni < 4; ni++) {
                uint32_t off = (uint32_t)(((wn * 32 + ni * 8 + g) * PAD_W) / 2 + i4 + ks * 8) * 4;
                bh[ni][0] = lds32(stBh + off);
                bh[ni][1] = lds32(stBh + off + 16);
                bl[ni][0] = lds32(stBl + off);
                bl[ni][1] = lds32(stBl + off + 16);
            }
            #pragma unroll
            for (int mi = 0; mi < 4; mi++) {
                uint32_t off = (uint32_t)(((wm * 64 + mi * 16 + g) * PAD_W) / 2 + i4 + ks * 8) * 4;
                uint32_t ah0 = lds32(stAh + off);
                uint32_t ah1 = lds32(stAh + off + 640);
                uint32_t ah2 = lds32(stAh + off + 16);
                uint32_t ah3 = lds32(stAh + off + 656);
                uint32_t al0 = lds32(stAl + off);
                uint32_t al1 = lds32(stAl + off + 640);
                uint32_t al2 = lds32(stAl + off + 16);
                uint32_t al3 = lds32(stAl + off + 656);
                #pragma unroll
                for (int ni = 0; ni < 4; ni++) {
                    mma16816(acc[mi][ni], ah0, ah1, ah2, ah3, bh[ni][0], bh[ni][1]);
                    mma16816(acc[mi][ni], ah0, ah1, ah2, ah3, bl[ni][0], bl[ni][1]);
                    mma16816(acc[mi][ni], al0, al1, al2, al3, bh[ni][0], bh[ni][1]);
                }
            }
        }
        __syncthreads();
    }

    #pragma unroll
    for (int mi = 0; mi < 4; mi++) {
        int row0 = bm + wm * 64 + mi * 16 + g;
        #pragma unroll
        for (int ni = 0; ni < 4; ni++) {
            int col = bn + wn * 32 + ni * 8 + i4 * 2;
            float v[4];
            v[0] = acc[mi][ni][0]; v[1] = acc[mi][ni][1];
            v[2] = acc[mi][ni][2]; v[3] = acc[mi][ni][3];
            if (EPI != 0) {
                float b0 = bias[col], b1 = bias[col + 1];
                v[0] += b0; v[1] += b1; v[2] += b0; v[3] += b1;
            }
            if (EPI == 2) {
                #pragma unroll
                for (int t = 0; t < 4; t++)
                    v[t] = 0.5f * v[t] * (1.0f + erff(v[t] * 0.70710678118654752f));
            }
            if (EPI == 1) {
                const float* r0 = res + (size_t)row0 * N + col;
                const float* r1 = r0 + 8 * (size_t)N;
                v[0] += r0[0]; v[1] += r0[1]; v[2] += r1[0]; v[3] += r1[1];
            }
            if (OUT == 0) {
                float* p0 = C + (size_t)row0 * N + col;
                float* p1 = p0 + 8 * (size_t)N;
                *(float2*)p0 = make_float2(v[0], v[1]);
                *(float2*)p1 = make_float2(v[2], v[3]);
            } else {
                size_t o0 = (size_t)row0 * N + col;
                size_t o1 = o0 + 8 * (size_t)N;
                uint32_t h, l;
                split_pair(v[0], v[1], h, l);
                *(uint32_t*)(Oh + o0) = h; *(uint32_t*)(Ol + o0) = l;
                split_pair(v[2], v[3], h, l);
                *(uint32_t*)(Oh + o1) = h; *(uint32_t*)(Ol + o1) = l;
            }
        }
    }
}

// ---------------- layernorm with bf16 hi/lo split output ----------------
__global__ void ln_split(const float* __restrict__ in, __nv_bfloat16* __restrict__ hi,
                         __nv_bfloat16* __restrict__ lo, const float* __restrict__ gw,
                         const float* __restrict__ bw) {
    int row = blockIdx.x;
    int tid = threadIdx.x;
    const float4* x4 = (const float4*)(in + (size_t)row * DD);
    float4 v = x4[tid];
    __shared__ float red[8];
    __shared__ float stat[2];
    float s = v.x + v.y + v.z + v.w;
    #pragma unroll
    for (int o = 16; o; o >>= 1) s += __shfl_xor_sync(0xffffffffu, s, o);
    if ((tid & 31) == 0) red[tid >> 5] = s;
    __syncthreads();
    if (tid < 32) {
        float t = (tid < 8) ? red[tid] : 0.f;
        #pragma unroll
        for (int o = 4; o; o >>= 1) t += __shfl_xor_sync(0xffffffffu, t, o);
        if (tid == 0) stat[0] = t * (1.0f / DD);
    }
    __syncthreads();
    float mu = stat[0];
    float a = v.x - mu, b = v.y - mu, c = v.z - mu, d = v.w - mu;
    float s2 = a*a + b*b + c*c + d*d;
    #pragma unroll
    for (int o = 16; o; o >>= 1) s2 += __shfl_xor_sync(0xffffffffu, s2, o);
    if ((tid & 31) == 0) red[tid >> 5] = s2;
    __syncthreads();
    if (tid < 32) {
        float t = (tid < 8) ? red[tid] : 0.f;
        #pragma unroll
        for (int o = 4; o; o >>= 1) t += __shfl_xor_sync(0xffffffffu, t, o);
        if (tid == 0) stat[1] = rsqrtf(t * (1.0f / DD) + 1e-5f);
    }
    __syncthreads();
    float rs = stat[1];
    float4 g4 = ((const float4*)gw)[tid];
    float4 b4 = ((const float4*)bw)[tid];
    float o0 = a*rs*g4.x + b4.x, o1 = b*rs*g4.y + b4.y;
    float o2 = c*rs*g4.z + b4.z, o3 = d*rs*g4.w + b4.w;
    uint32_t h, l;
    size_t base = (size_t)row * DD + tid * 4;
    split_pair(o0, o1, h, l);
    *(uint32_t*)(hi + base) = h; *(uint32_t*)(lo + base) = l;
    split_pair(o2, o3, h, l);
    *(uint32_t*)(hi + base + 2) = h; *(uint32_t*)(lo + base + 2) = l;
}

// ---------------- per-head rank expansion -> bf16 [B,H,S,DH] ----------------
__global__ void expand_heads(const float* __restrict__ Xr, const float* __restrict__ Vh,
                             const float* __restrict__ bias, __nv_bfloat16* __restrict__ out,
                             int ld) {
    int bh = blockIdx.y;
    int b  = bh / HH;
    int h  = bh % HH;
    int s0 = blockIdx.x * 64;
    __shared__ float Vs[RA][DHD];
    __shared__ float Xs[64][RA];
    int tid = threadIdx.x;
    const float* vp = Vh + (size_t)h * RA * DHD;
    for (int i = tid; i < RA * DHD / 4; i += 256)
        ((float4*)Vs)[i] = ((const float4*)vp)[i];
    for (int i = tid; i < 64 * RA / 4; i += 256) {
        int r = i >> 3, c4 = (i & 7) << 2;
        *(float4*)&Xs[r][c4] =
            *(const float4*)(Xr + (size_t)(b * SS + s0 + r) * ld + h * RA + c4);
    }
    __syncthreads();
    for (int i = tid; i < 64 * DHD; i += 256) {
        int sl = i >> 6, e = i & 63;
        float acc = bias[h * DHD + e];
        #pragma unroll
        for (int r = 0; r < RA; r++) acc = fmaf(Xs[sl][r], Vs[r][e], acc);
        out[((size_t)bh * SS + s0 + sl) * DHD + e] = __float2bfloat16(acc);
    }
}

// ---------------- flash attention, mma.sync bf16, causal ----------------
// CTA: 128 threads (4 warps), 64-row Q tile, 64-col S tiles, cp.async 2-stage.
// Output: merged-head hi/lo bf16 split written directly to [B,S,D] buffers.
__global__ void __launch_bounds__(128)
flash_mma(const __nv_bfloat16* __restrict__ Qg_, const __nv_bfloat16* __restrict__ Kg_,
          const __nv_bfloat16* __restrict__ Vg_, __nv_bfloat16* __restrict__ Oh,
          __nv_bfloat16* __restrict__ Ol) {
    __shared__ __align__(16) __nv_bfloat16 Qs[64*72];
    __shared__ __align__(16) __nv_bfloat16 KVs[2][2][64*72];
    int bh = blockIdx.y;
    int b = bh >> 4, h = bh & 15;
    int m0 = ((int)gridDim.x - 1 - (int)blockIdx.x) * 64;
    int tid = threadIdx.x, wid = tid >> 5, lane = tid & 31;
    int g = lane >> 2, i4 = lane & 3;
    const __nv_bfloat16* Qg = Qg_ + ((size_t)bh * SS + m0) * DHD;
    const __nv_bfloat16* Kg = Kg_ + (size_t)bh * SS * DHD;
    const __nv_bfloat16* Vg = Vg_ + (size_t)bh * SS * DHD;
    uint32_t sQ = smem_u32(Qs);
    uint32_t sKV = smem_u32(KVs);
    const uint32_t VOFF = 64*72*2;
    const uint32_t STGB = 2*VOFF;

    #pragma unroll
    for (int it = 0; it < 4; it++) {
        int i = tid + it * 128; int r = i >> 3, q = i & 7;
        cpa16(sQ + (uint32_t)(r*72 + q*8)*2, Qg + (size_t)r*DHD + q*8);
    }
    CP_COMMIT();
    #pragma unroll
    for (int it = 0; it < 4; it++) {
        int i = tid + it * 128; int r = i >> 3, q = i & 7;
        uint32_t so = (uint32_t)(r*72 + q*8)*2;
        cpa16(sKV + so,        Kg + (size_t)r*DHD + q*8);
        cpa16(sKV + VOFF + so, Vg + (size_t)r*DHD + q*8);
    }
    CP_COMMIT();
    CP_WAIT(1);
    __syncthreads();

    // Q fragments held in registers for the whole loop
    uint32_t qf[4][4];
    {
        uint32_t r0 = sQ + (uint32_t)((wid*16 + g)*36)*4;
        uint32_t r8 = r0 + 8*36*4;
        #pragma unroll
        for (int t = 0; t < 4; t++) {
            qf[t][0] = lds32(r0 + (uint32_t)(t*8 + i4)*4);
            qf[t][1] = lds32(r8 + (uint32_t)(t*8 + i4)*4);
            qf[t][2] = lds32(r0 + (uint32_t)(t*8 + i4 + 4)*4);
            qf[t][3] = lds32(r8 + (uint32_t)(t*8 + i4 + 4)*4);
        }
    }

    float o[8][4];
    #pragma unroll
    for (int u = 0; u < 8; u++) { o[u][0]=o[u][1]=o[u][2]=o[u][3]=0.f; }
    float m0f = -1e30f, m1f = -1e30f, l0f = 0.f, l1f = 0.f;

    int NT = m0/64 + 1;
    for (int ti = 0; ti < NT; ti++) {
        if (ti + 1 < NT) {
            const __nv_bfloat16* Kp = Kg + (size_t)(ti+1)*64*DHD;
            const __nv_bfloat16* Vp = Vg + (size_t)(ti+1)*64*DHD;
            uint32_t sst = sKV + ((uint32_t)(ti+1) & 1) * STGB;
            #pragma unroll
            for (int it = 0; it < 4; it++) {
                int i = tid + it * 128; int r = i >> 3, q = i & 7;
                uint32_t so = (uint32_t)(r*72 + q*8)*2;
                cpa16(sst + so,        Kp + (size_t)r*DHD + q*8);
                cpa16(sst + VOFF + so, Vp + (size_t)r*DHD + q*8);
            }
            CP_COMMIT();
            CP_WAIT(1);
        } else {
            CP_WAIT(0);
        }
        __syncthreads();
        uint32_t sK = sKV + ((uint32_t)ti & 1) * STGB;
        uint32_t sV = sK + VOFF;

        // S = Q K^T
        float s[8][4];
        #pragma unroll
        for (int nt = 0; nt < 8; nt++) { s[nt][0]=s[nt][1]=s[nt][2]=s[nt][3]=0.f; }
        #pragma unroll
        for (int t = 0; t < 4; t++) {
            #pragma unroll
            for (int nt = 0; nt < 8; nt++) {
                uint32_t kb = sK + (uint32_t)((nt*8 + g)*36 + t*8 + i4)*4;
                uint32_t b0 = lds32(kb);
                uint32_t b1 = lds32(kb + 16);
                mma16816(s[nt], qf[t][0], qf[t][1], qf[t][2], qf[t][3], b0, b1);
            }
        }

        const float scale = 0.125f;
        bool diag = (ti == NT - 1);
        int grow0 = m0 + wid*16 + g;
        int grow1 = grow0 + 8;
        float mx0 = -1e30f, mx1 = -1e30f;
        #pragma unroll
        for (int nt = 0; nt < 8; nt++) {
            int c0 = ti*64 + nt*8 + 2*i4;
            float v0 = s[nt][0]*scale, v1 = s[nt][1]*scale;
            float v2 = s[nt][2]*scale, v3 = s[nt][3]*scale;
            if (diag) {
                if (c0     > grow0) v0 = -1e30f;
                if (c0 + 1 > grow0) v1 = -1e30f;
                if (c0     > grow1) v2 = -1e30f;
                if (c0 + 1 > grow1) v3 = -1e30f;
            }
            s[nt][0]=v0; s[nt][1]=v1; s[nt][2]=v2; s[nt][3]=v3;
            mx0 = fmaxf(mx0, fmaxf(v0, v1));
            mx1 = fmaxf(mx1, fmaxf(v2, v3));
        }
        mx0 = fmaxf(mx0, __shfl_xor_sync(0xffffffffu, mx0, 1));
        mx0 = fmaxf(mx0, __shfl_xor_sync(0xffffffffu, mx0, 2));
        mx1 = fmaxf(mx1, __shfl_xor_sync(0xffffffffu, mx1, 1));
        mx1 = fmaxf(mx1, __shfl_xor_sync(0xffffffffu, mx1, 2));
        float nm0 = fmaxf(m0f, mx0), nm1 = fmaxf(m1f, mx1);
        float a0 = __expf(m0f - nm0), a1 = __expf(m1f - nm1);
        float sum0 = 0.f, sum1 = 0.f;
        #pragma unroll
        for (int nt = 0; nt < 8; nt++) {
            float p0 = __expf(s[nt][0] - nm0);
            float p1 = __expf(s[nt][1] - nm0);
            float p2 = __expf(s[nt][2] - nm1);
            float p3 = __expf(s[nt][3] - nm1);
            s[nt][0]=p0; s[nt][1]=p1; s[nt][2]=p2; s[nt][3]=p3;
            sum0 += p0 + p1; sum1 += p2 + p3;
        }
        sum0 += __shfl_xor_sync(0xffffffffu, sum0, 1);
        sum0 += __shfl_xor_sync(0xffffffffu, sum0, 2);
        sum1 += __shfl_xor_sync(0xffffffffu, sum1, 1);
        sum1 += __shfl_xor_sync(0xffffffffu, sum1, 2);
        l0f = l0f * a0 + sum0; l1f = l1f * a1 + sum1;
        m0f = nm0; m1f = nm1;
        #pragma unroll
        for (int u = 0; u < 8; u++) {
            o[u][0] *= a0; o[u][1] *= a0; o[u][2] *= a1; o[u][3] *= a1;
        }

        // O += P V   (P packed to bf16 A-fragments in registers)
        #pragma unroll
        for (int t = 0; t < 4; t++) {
            uint32_t pa0 = packbf(s[2*t][0],   s[2*t][1]);
            uint32_t pa1 = packbf(s[2*t][2],   s[2*t][3]);
            uint32_t pa2 = packbf(s[2*t+1][0], s[2*t+1][1]);
            uint32_t pa3 = packbf(s[2*t+1][2], s[2*t+1][3]);
            #pragma unroll
            for (int u = 0; u < 4; u++) {
                uint32_t addr = sV + (uint32_t)((t*16 + (lane & 15))*36
                                                + u*8 + ((lane >> 4) << 2))*4;
                uint32_t r0, r1, r2, r3;
                ldmx4t(r0, r1, r2, r3, addr);
                mma16816(o[2*u],     pa0, pa1, pa2, pa3, r0, r1);
                mma16816(o[2*u + 1], pa0, pa1, pa2, pa3, r2, r3);
            }
        }
        __syncthreads();
    }

    // epilogue: merged heads, hi/lo split
    float inv0 = 1.f / l0f, inv1 = 1.f / l1f;
    int r0g = m0 + wid*16 + g;
    size_t base0 = ((size_t)b * SS + r0g) * DD + h * DHD;
    size_t base1 = base0 + 8 * (size_t)DD;
    #pragma unroll
    for (int u = 0; u < 8; u++) {
        int col = u*8 + 2*i4;
        uint32_t hh, ll;
        split_pair(o[u][0]*inv0, o[u][1]*inv0, hh, ll);
        *(uint32_t*)(Oh + base0 + col) = hh;
        *(uint32_t*)(Ol + base0 + col) = ll;
        split_pair(o[u][2]*inv1, o[u][3]*inv1, hh, ll);
        *(uint32_t*)(Oh + base1 + col) = hh;
        *(uint32_t*)(Ol + base1 + col) = ll;
    }
}

// ---------------- host launcher ----------------
extern "C" void kernel_launch(void* const* d_in, const int* in_sizes, int n_in,
                              void* d_out, int out_size) {
    const float* hidden = (const float*)d_in[0];
    const float* ln1_g  = (const float*)d_in[1];
    const float* ln1_b  = (const float*)d_in[2];
    const float* ln2_g  = (const float*)d_in[3];
    const float* ln2_b  = (const float*)d_in[4];
    const float* q_U = (const float*)d_in[5];
    const float* q_V = (const float*)d_in[6];
    const float* q_b = (const float*)d_in[7];
    const float* k_U = (const float*)d_in[8];
    const float* k_V = (const float*)d_in[9];
    const float* k_b = (const float*)d_in[10];
    const float* v_U = (const float*)d_in[11];
    const float* v_V = (const float*)d_in[12];
    const float* v_b = (const float*)d_in[13];
    const float* out_U = (const float*)d_in[14];
    const float* out_V = (const float*)d_in[15];
    const float* out_b = (const float*)d_in[16];
    const float* fc1_U = (const float*)d_in[17];
    const float* fc1_V = (const float*)d_in[18];
    const float* fc1_b = (const float*)d_in[19];
    const float* fc2_U = (const float*)d_in[20];
    const float* fc2_V = (const float*)d_in[21];
    const float* fc2_b = (const float*)d_in[22];
    float* out = (float*)d_out;

    float *QKVr, *hb;
    __nv_bfloat16 *Ah, *Al, *Ch, *Cl, *Qbf, *Kbf, *Vbf;
    __nv_bfloat16 *Bqkvh, *Bqkvl, *Bouh, *Boul, *Bovh, *Bovl;
    __nv_bfloat16 *Bf1uh, *Bf1ul, *Bf1vh, *Bf1vl, *Bf2uh, *Bf2ul, *Bf2vh, *Bf2vl;
    cudaGetSymbolAddress((void**)&QKVr, g_QKVr);
    cudaGetSymbolAddress((void**)&hb,   g_h);
    cudaGetSymbolAddress((void**)&Ah,   g_Ah);
    cudaGetSymbolAddress((void**)&Al,   g_Al);
    cudaGetSymbolAddress((void**)&Ch,   g_Ch);
    cudaGetSymbolAddress((void**)&Cl,   g_Cl);
    cudaGetSymbolAddress((void**)&Qbf,  g_Qbf);
    cudaGetSymbolAddress((void**)&Kbf,  g_Kbf);
    cudaGetSymbolAddress((void**)&Vbf,  g_Vbf);
    cudaGetSymbolAddress((void**)&Bqkvh, g_Bqkvh);
    cudaGetSymbolAddress((void**)&Bqkvl, g_Bqkvl);
    cudaGetSymbolAddress((void**)&Bouh, g_Bouh);
    cudaGetSymbolAddress((void**)&Boul, g_Boul);
    cudaGetSymbolAddress((void**)&Bovh, g_Bovh);
    cudaGetSymbolAddress((void**)&Bovl, g_Bovl);
    cudaGetSymbolAddress((void**)&Bf1uh, g_Bf1uh);
    cudaGetSymbolAddress((void**)&Bf1ul, g_Bf1ul);
    cudaGetSymbolAddress((void**)&Bf1vh, g_Bf1vh);
    cudaGetSymbolAddress((void**)&Bf1vl, g_Bf1vl);
    cudaGetSymbolAddress((void**)&Bf2uh, g_Bf2uh);
    cudaGetSymbolAddress((void**)&Bf2ul, g_Bf2ul);
    cudaGetSymbolAddress((void**)&Bf2vh, g_Bf2vh);
    cudaGetSymbolAddress((void**)&Bf2vl, g_Bf2vl);

    cudaFuncSetAttribute(gemm_mma<0,0>, cudaFuncAttributeMaxDynamicSharedMemorySize, GM_SMEM);
    cudaFuncSetAttribute(gemm_mma<0,1>, cudaFuncAttributeMaxDynamicSharedMemorySize, GM_SMEM);
    cudaFuncSetAttribute(gemm_mma<1,0>, cudaFuncAttributeMaxDynamicSharedMemorySize, GM_SMEM);
    cudaFuncSetAttribute(gemm_mma<2,1>, cudaFuncAttributeMaxDynamicSharedMemorySize, GM_SMEM);

    dim3 wblk(32, 8);
    // weight conversions
    convW<<<dim3(HR/32, DD/32), wblk>>>(q_U, Bqkvh,           Bqkvl,           DD, HR);
    convW<<<dim3(HR/32, DD/32), wblk>>>(k_U, Bqkvh + HR*DD,   Bqkvl + HR*DD,   DD, HR);
    convW<<<dim3(HR/32, DD/32), wblk>>>(v_U, Bqkvh + 2*HR*DD, Bqkvl + 2*HR*DD, DD, HR);
    convW<<<dim3(R_OUT/32, DD/32), wblk>>>(out_U, Bouh, Boul, DD, R_OUT);
    convW<<<dim3(DD/32, R_OUT/32), wblk>>>(out_V, Bovh, Bovl, R_OUT, DD);
    convW<<<dim3(R_FC/32, DD/32), wblk>>>(fc1_U, Bf1uh, Bf1ul, DD, R_FC);
    convW<<<dim3(II/32, R_FC/32), wblk>>>(fc1_V, Bf1vh, Bf1vl, R_FC, II);
    convW<<<dim3(R_FC/32, II/32), wblk>>>(fc2_U, Bf2uh, Bf2ul, II, R_FC);
    convW<<<dim3(DD/32, R_FC/32), wblk>>>(fc2_V, Bf2vh, Bf2vl, R_FC, DD);

    // 1. LN1 (split output)
    ln_split<<<NROW, 256>>>(hidden, Ah, Al, ln1_g, ln1_b);
    // 2. fused qkv rank projection -> [4096, 1536] fp32
    gemm_mma<0,0><<<dim3(HR3/128, NROW/128), 256, GM_SMEM>>>(Ah, Al, Bqkvh, Bqkvl, QKVr,
        nullptr, nullptr, nullptr, nullptr, NROW, HR3, DD);
    // 3. per-head expansion -> bf16 [B,H,S,DH]
    expand_heads<<<dim3(SS/64, BB*HH), 256>>>(QKVr,        q_V, q_b, Qbf, HR3);
    expand_heads<<<dim3(SS/64, BB*HH), 256>>>(QKVr + HR,   k_V, k_b, Kbf, HR3);
    expand_heads<<<dim3(SS/64, BB*HH), 256>>>(QKVr + 2*HR, v_V, v_b, Vbf, HR3);
    // 4. flash attention (mma) -> merged-head split Y in Ch/Cl
    flash_mma<<<dim3(SS/64, BB*HH), 128>>>(Qbf, Kbf, Vbf, Ch, Cl);
    // 5. out projection + residual
    gemm_mma<0,1><<<dim3(R_OUT/128, NROW/128), 256, GM_SMEM>>>(Ch, Cl, Bouh, Boul, nullptr,
        Ah, Al, nullptr, nullptr, NROW, R_OUT, DD);
    gemm_mma<1,0><<<dim3(DD/128, NROW/128), 256, GM_SMEM>>>(Ah, Al, Bovh, Bovl, hb,
        nullptr, nullptr, out_b, hidden, NROW, DD, R_OUT);
    // 6. LN2 (split output)
    ln_split<<<NROW, 256>>>(hb, Ch, Cl, ln2_g, ln2_b);
    // 7. MLP
    gemm_mma<0,1><<<dim3(R_FC/128, NROW/128), 256, GM_SMEM>>>(Ch, Cl, Bf1uh, Bf1ul, nullptr,
        Ah, Al, nullptr, nullptr, NROW, R_FC, DD);
    gemm_mma<2,1><<<dim3(II/128, NROW/128), 256, GM_SMEM>>>(Ah, Al, Bf1vh, Bf1vl, nullptr,
        Ch, Cl, fc1_b, nullptr, NROW, II, R_FC);
    gemm_mma<0,1><<<dim3(R_FC/128, NROW/128), 256, GM_SMEM>>>(Ch, Cl, Bf2uh, Bf2ul, nullptr,
        Ah, Al, nullptr, nullptr, NROW, R_FC, II);
    gemm_mma<1,0><<<dim3(DD/128, NROW/128), 256, GM_SMEM>>>(Ah, Al, Bf2vh, Bf2vl, out,
        nullptr, nullptr, fc2_b, hb, NROW, DD, R_FC);
}

// round 5
// speedup vs baseline: 6.4018x; 1.7248x over previous
#include <cuda_runtime.h>
#include <cuda_fp16.h>
#include <math.h>
#include <stdint.h>

// ---------------- problem constants ----------------
#define BB 2
#define SS 2048
#define DD 1024
#define HH 16
#define DHD 64
#define NROW (BB*SS)      // 4096
#define RA 32
#define HR 512
#define HR3 1536
#define R_OUT 512
#define II 4096
#define R_FC 512

// ---------------- device scratch ----------------
__device__ float g_QKVr[NROW*HR3];
__device__ float g_h   [NROW*DD];

__device__ __align__(1024) __half g_Q16[NROW*DD];
__device__ __align__(1024) __half g_K16[NROW*DD];
__device__ __align__(1024) __half g_V16[NROW*DD];

// fp16 activation ping-pong
__device__ __align__(1024) __half g_A16[NROW*DD];
__device__ __align__(1024) __half g_C16[NROW*II];

// fp16 weights (transposed to [N,K])
__device__ __align__(1024) __half g_Wqkv[HR3*DD];
__device__ __align__(1024) __half g_Wou [R_OUT*DD];
__device__ __align__(1024) __half g_Wov [DD*R_OUT];
__device__ __align__(1024) __half g_Wf1u[R_FC*DD];
__device__ __align__(1024) __half g_Wf1v[II*R_FC];
__device__ __align__(1024) __half g_Wf2u[R_FC*II];
__device__ __align__(1024) __half g_Wf2v[DD*R_FC];

// ================= low-level helpers =================
__device__ __forceinline__ uint32_t smem_u32(const void* p) {
    uint32_t a;
    asm("{ .reg .u64 t; cvta.to.shared.u64 t, %1; cvt.u32.u64 %0, t; }" : "=r"(a) : "l"(p));
    return a;
}
__device__ __forceinline__ void cpa16(uint32_t dst, const void* src) {
    asm volatile("cp.async.cg.shared.global [%0], [%1], 16;" :: "r"(dst), "l"(src) : "memory");
}
#define CP_COMMIT() asm volatile("cp.async.commit_group;" ::: "memory")
#define CP_WAIT(n)  asm volatile("cp.async.wait_group %0;" :: "n"(n) : "memory")

__device__ __forceinline__ uint32_t lds32(uint32_t a) {
    uint32_t v;
    asm("ld.shared.b32 %0, [%1];" : "=r"(v) : "r"(a));
    return v;
}
__device__ __forceinline__ void mma16816(float* c, uint32_t a0, uint32_t a1, uint32_t a2,
                                         uint32_t a3, uint32_t b0, uint32_t b1) {
    asm volatile(
        "mma.sync.aligned.m16n8k16.row.col.f32.f16.f16.f32 "
        "{%0,%1,%2,%3}, {%4,%5,%6,%7}, {%8,%9}, {%0,%1,%2,%3};"
        : "+f"(c[0]), "+f"(c[1]), "+f"(c[2]), "+f"(c[3])
        : "r"(a0), "r"(a1), "r"(a2), "r"(a3), "r"(b0), "r"(b1));
}
__device__ __forceinline__ void ldmx4t(uint32_t& r0, uint32_t& r1, uint32_t& r2,
                                       uint32_t& r3, uint32_t addr) {
    asm volatile("ldmatrix.sync.aligned.m8n8.x4.trans.shared.b16 {%0,%1,%2,%3}, [%4];"
                 : "=r"(r0), "=r"(r1), "=r"(r2), "=r"(r3) : "r"(addr));
}
__device__ __forceinline__ uint32_t packh(float a, float b) {
    __half2 t = __float22half2_rn(make_float2(a, b));
    return *(uint32_t*)&t;
}

// ---------------- weight transpose + fp16 convert ----------------
__global__ void convW(const float* __restrict__ W, __half* __restrict__ out, int K, int N) {
    __shared__ float t[32][33];
    int n0 = blockIdx.x * 32, k0 = blockIdx.y * 32;
    int tx = threadIdx.x, ty = threadIdx.y;  // 32x8
    #pragma unroll
    for (int i = 0; i < 4; i++)
        t[ty + 8*i][tx] = W[(size_t)(k0 + ty + 8*i) * N + n0 + tx];
    __syncthreads();
    #pragma unroll
    for (int i = 0; i < 4; i++)
        out[(size_t)(n0 + ty + 8*i) * K + k0 + tx] = __float2half(t[tx][ty + 8*i]);
}

// ---------------- mma.sync fp16 GEMM: C[M,N] = A[M,K] @ B[N,K]^T ----------
// 128x128 CTA tile, BK=32, 8 warps (2x4), warp tile 64x32, cp.async 2-stage.
// EPI: 0=none, 1=bias+residual, 2=bias+GELU ; OUT: 0=fp32, 1=fp16
#define PAD_W 40
#define MAT_B (128*PAD_W*2)   // 10240
#define STG_B (2*MAT_B)       // 20480
#define GM_SMEM (2*STG_B)     // 40960

__device__ __forceinline__ void copy_stage(uint32_t sst,
        const __half* __restrict__ Ap, const __half* __restrict__ Bp,
        int K, int k0, int tid) {
    #pragma unroll
    for (int it = 0; it < 2; it++) {
        int i = tid + it * 256;
        int row = i >> 2, q = i & 3;
        size_t go = (size_t)row * K + k0 + q * 8;
        uint32_t so = (uint32_t)(row * PAD_W + q * 8) * 2;
        cpa16(sst + so,         Ap + go);
        cpa16(sst + MAT_B + so, Bp + go);
    }
}

template<int EPI, int OUT>
__global__ void __launch_bounds__(256, 2)
gemm_mma(const __half* __restrict__ A, const __half* __restrict__ B,
         float* __restrict__ C, __half* __restrict__ O16,
         const float* __restrict__ bias, const float* __restrict__ res,
         int M, int N, int K) {
    extern __shared__ char smem_raw[];
    uint32_t sbase = smem_u32(smem_raw);
    int tid = threadIdx.x;
    int wid = tid >> 5, lane = tid & 31;
    int wm = wid >> 2, wn = wid & 3;
    int g = lane >> 2, i4 = lane & 3;
    int bm = blockIdx.y * 128, bn = blockIdx.x * 128;

    const __half* Ap = A + (size_t)bm * K;
    const __half* Bp = B + (size_t)bn * K;

    float acc[4][4][4];
    #pragma unroll
    for (int a = 0; a < 4; a++)
        #pragma unroll
        for (int b = 0; b < 4; b++)
            #pragma unroll
            for (int c = 0; c < 4; c++) acc[a][b][c] = 0.f;

    int NC = K >> 5;
    copy_stage(sbase, Ap, Bp, K, 0, tid);
    CP_COMMIT();

    for (int c = 0; c < NC; c++) {
        if (c + 1 < NC) {
            copy_stage(sbase + ((c + 1) & 1) * STG_B, Ap, Bp, K, (c + 1) << 5, tid);
            CP_COMMIT();
            CP_WAIT(1);
        } else {
            CP_WAIT(0);
        }
        __syncthreads();

        uint32_t st = sbase + (c & 1) * STG_B;
        uint32_t stA = st, stB = st + MAT_B;

        #pragma unroll
        for (int ks = 0; ks < 2; ks++) {
            uint32_t bf[4][2];
            #pragma unroll
            for (int ni = 0; ni < 4; ni++) {
                uint32_t off = (uint32_t)((wn * 32 + ni * 8 + g) * (PAD_W/2) + i4 + ks * 8) * 4;
                bf[ni][0] = lds32(stB + off);
                bf[ni][1] = lds32(stB + off + 16);
            }
            #pragma unroll
            for (int mi = 0; mi < 4; mi++) {
                uint32_t off = (uint32_t)((wm * 64 + mi * 16 + g) * (PAD_W/2) + i4 + ks * 8) * 4;
                uint32_t a0 = lds32(stA + off);
                uint32_t a1 = lds32(stA + off + 640);
                uint32_t a2 = lds32(stA + off + 16);
                uint32_t a3 = lds32(stA + off + 656);
                #pragma unroll
                for (int ni = 0; ni < 4; ni++)
                    mma16816(acc[mi][ni], a0, a1, a2, a3, bf[ni][0], bf[ni][1]);
            }
        }
        __syncthreads();
    }

    #pragma unroll
    for (int mi = 0; mi < 4; mi++) {
        int row0 = bm + wm * 64 + mi * 16 + g;
        #pragma unroll
        for (int ni = 0; ni < 4; ni++) {
            int col = bn + wn * 32 + ni * 8 + i4 * 2;
            float v[4];
            v[0] = acc[mi][ni][0]; v[1] = acc[mi][ni][1];
            v[2] = acc[mi][ni][2]; v[3] = acc[mi][ni][3];
            if (EPI != 0) {
                float b0 = bias[col], b1 = bias[col + 1];
                v[0] += b0; v[1] += b1; v[2] += b0; v[3] += b1;
            }
            if (EPI == 2) {
                #pragma unroll
                for (int t = 0; t < 4; t++)
                    v[t] = 0.5f * v[t] * (1.0f + erff(v[t] * 0.70710678118654752f));
            }
            if (EPI == 1) {
                const float* r0 = res + (size_t)row0 * N + col;
                const float* r1 = r0 + 8 * (size_t)N;
                v[0] += r0[0]; v[1] += r0[1]; v[2] += r1[0]; v[3] += r1[1];
            }
            if (OUT == 0) {
                float* p0 = C + (size_t)row0 * N + col;
                float* p1 = p0 + 8 * (size_t)N;
                *(float2*)p0 = make_float2(v[0], v[1]);
                *(float2*)p1 = make_float2(v[2], v[3]);
            } else {
                size_t o0 = (size_t)row0 * N + col;
                size_t o1 = o0 + 8 * (size_t)N;
                *(uint32_t*)(O16 + o0) = packh(v[0], v[1]);
                *(uint32_t*)(O16 + o1) = packh(v[2], v[3]);
            }
        }
    }
}

// ---------------- layernorm with fp16 output ----------------
__global__ void ln_half(const float* __restrict__ in, __half* __restrict__ out,
                        const float* __restrict__ gw, const float* __restrict__ bw) {
    int row = blockIdx.x;
    int tid = threadIdx.x;
    const float4* x4 = (const float4*)(in + (size_t)row * DD);
    float4 v = x4[tid];
    __shared__ float red[8];
    __shared__ float stat[2];
    float s = v.x + v.y + v.z + v.w;
    #pragma unroll
    for (int o = 16; o; o >>= 1) s += __shfl_xor_sync(0xffffffffu, s, o);
    if ((tid & 31) == 0) red[tid >> 5] = s;
    __syncthreads();
    if (tid < 32) {
        float t = (tid < 8) ? red[tid] : 0.f;
        #pragma unroll
        for (int o = 4; o; o >>= 1) t += __shfl_xor_sync(0xffffffffu, t, o);
        if (tid == 0) stat[0] = t * (1.0f / DD);
    }
    __syncthreads();
    float mu = stat[0];
    float a = v.x - mu, b = v.y - mu, c = v.z - mu, d = v.w - mu;
    float s2 = a*a + b*b + c*c + d*d;
    #pragma unroll
    for (int o = 16; o; o >>= 1) s2 += __shfl_xor_sync(0xffffffffu, s2, o);
    if ((tid & 31) == 0) red[tid >> 5] = s2;
    __syncthreads();
    if (tid < 32) {
        float t = (tid < 8) ? red[tid] : 0.f;
        #pragma unroll
        for (int o = 4; o; o >>= 1) t += __shfl_xor_sync(0xffffffffu, t, o);
        if (tid == 0) stat[1] = rsqrtf(t * (1.0f / DD) + 1e-5f);
    }
    __syncthreads();
    float rs = stat[1];
    float4 g4 = ((const float4*)gw)[tid];
    float4 b4 = ((const float4*)bw)[tid];
    size_t base = (size_t)row * DD + tid * 4;
    *(uint32_t*)(out + base)     = packh(a*rs*g4.x + b4.x, b*rs*g4.y + b4.y);
    *(uint32_t*)(out + base + 2) = packh(c*rs*g4.z + b4.z, d*rs*g4.w + b4.w);
}

// ---------------- fused per-head rank expansion (q,k,v via blockIdx.z) -----
__global__ void expand3(const float* __restrict__ Xr,
                        const float* __restrict__ qV, const float* __restrict__ kV,
                        const float* __restrict__ vV, const float* __restrict__ qb,
                        const float* __restrict__ kb, const float* __restrict__ vb,
                        __half* __restrict__ Qo, __half* __restrict__ Ko,
                        __half* __restrict__ Vo) {
    int which = blockIdx.z;
    const float* Vh = (which == 0) ? qV : (which == 1) ? kV : vV;
    const float* bias = (which == 0) ? qb : (which == 1) ? kb : vb;
    __half* out = (which == 0) ? Qo : (which == 1) ? Ko : Vo;
    const float* X = Xr + which * HR;

    int bh = blockIdx.y;
    int b  = bh / HH;
    int h  = bh % HH;
    int s0 = blockIdx.x * 64;
    __shared__ float Vs[RA][DHD];
    __shared__ float Xs[64][RA];
    int tid = threadIdx.x;
    const float* vp = Vh + (size_t)h * RA * DHD;
    for (int i = tid; i < RA * DHD / 4; i += 256)
        ((float4*)Vs)[i] = ((const float4*)vp)[i];
    for (int i = tid; i < 64 * RA / 4; i += 256) {
        int r = i >> 3, c4 = (i & 7) << 2;
        *(float4*)&Xs[r][c4] =
            *(const float4*)(X + (size_t)(b * SS + s0 + r) * HR3 + h * RA + c4);
    }
    __syncthreads();
    for (int i = tid; i < 64 * DHD; i += 256) {
        int sl = i >> 6, e = i & 63;
        float acc = bias[h * DHD + e];
        #pragma unroll
        for (int r = 0; r < RA; r++) acc = fmaf(Xs[sl][r], Vs[r][e], acc);
        out[((size_t)bh * SS + s0 + sl) * DHD + e] = __float2half(acc);
    }
}

// ---------------- flash attention, fp16 mma, 128-row Q tile, causal --------
// 256 threads (8 warps), 64-col K/V tiles, cp.async double buffer.
#define FA_SMEM ((128*72 + 2*2*64*72) * 2)   // 55296 bytes
__global__ void __launch_bounds__(256)
flash_mma(const __half* __restrict__ Qg_, const __half* __restrict__ Kg_,
          const __half* __restrict__ Vg_, __half* __restrict__ O16) {
    extern __shared__ char fsm[];
    uint32_t sQ = smem_u32(fsm);
    uint32_t sKV = sQ + 128*72*2;
    const uint32_t VOFF = 64*72*2;   // 9216
    const uint32_t STGB = 2*VOFF;    // 18432
    int bh = blockIdx.y;
    int b = bh >> 4, h = bh & 15;
    int m0 = ((int)gridDim.x - 1 - (int)blockIdx.x) * 128;
    int tid = threadIdx.x, wid = tid >> 5, lane = tid & 31;
    int g = lane >> 2, i4 = lane & 3;
    const __half* Qg = Qg_ + ((size_t)bh * SS + m0) * DHD;
    const __half* Kg = Kg_ + (size_t)bh * SS * DHD;
    const __half* Vg = Vg_ + (size_t)bh * SS * DHD;

    #pragma unroll
    for (int it = 0; it < 4; it++) {
        int i = tid + it * 256; int r = i >> 3, q = i & 7;
        cpa16(sQ + (uint32_t)(r*72 + q*8)*2, Qg + (size_t)r*DHD + q*8);
    }
    CP_COMMIT();
    #pragma unroll
    for (int it = 0; it < 2; it++) {
        int i = tid + it * 256; int r = i >> 3, q = i & 7;
        uint32_t so = (uint32_t)(r*72 + q*8)*2;
        cpa16(sKV + so,        Kg + (size_t)r*DHD + q*8);
        cpa16(sKV + VOFF + so, Vg + (size_t)r*DHD + q*8);
    }
    CP_COMMIT();
    CP_WAIT(1);
    __syncthreads();

    uint32_t qf[4][4];
    {
        uint32_t r0 = sQ + (uint32_t)((wid*16 + g)*36)*4;
        uint32_t r8 = r0 + 8*36*4;
        #pragma unroll
        for (int t = 0; t < 4; t++) {
            qf[t][0] = lds32(r0 + (uint32_t)(t*8 + i4)*4);
            qf[t][1] = lds32(r8 + (uint32_t)(t*8 + i4)*4);
            qf[t][2] = lds32(r0 + (uint32_t)(t*8 + i4 + 4)*4);
            qf[t][3] = lds32(r8 + (uint32_t)(t*8 + i4 + 4)*4);
        }
    }

    float o[8][4];
    #pragma unroll
    for (int u = 0; u < 8; u++) { o[u][0]=o[u][1]=o[u][2]=o[u][3]=0.f; }
    float m0f = -1e30f, m1f = -1e30f, l0f = 0.f, l1f = 0.f;

    int NT = m0/64 + 2;
    for (int ti = 0; ti < NT; ti++) {
        if (ti + 1 < NT) {
            const __half* Kp = Kg + (size_t)(ti+1)*64*DHD;
            const __half* Vp = Vg + (size_t)(ti+1)*64*DHD;
            uint32_t sst = sKV + ((uint32_t)(ti+1) & 1) * STGB;
            #pragma unroll
            for (int it = 0; it < 2; it++) {
                int i = tid + it * 256; int r = i >> 3, q = i & 7;
                uint32_t so = (uint32_t)(r*72 + q*8)*2;
                cpa16(sst + so,        Kp + (size_t)r*DHD + q*8);
                cpa16(sst + VOFF + so, Vp + (size_t)r*DHD + q*8);
            }
            CP_COMMIT();
            CP_WAIT(1);
        } else {
            CP_WAIT(0);
        }
        __syncthreads();
        uint32_t sK = sKV + ((uint32_t)ti & 1) * STGB;
        uint32_t sV = sK + VOFF;

        // S = Q K^T
        float s[8][4];
        #pragma unroll
        for (int nt = 0; nt < 8; nt++) { s[nt][0]=s[nt][1]=s[nt][2]=s[nt][3]=0.f; }
        #pragma unroll
        for (int t = 0; t < 4; t++) {
            #pragma unroll
            for (int nt = 0; nt < 8; nt++) {
                uint32_t kb = sK + (uint32_t)((nt*8 + g)*36 + t*8 + i4)*4;
                uint32_t b0 = lds32(kb);
                uint32_t b1 = lds32(kb + 16);
                mma16816(s[nt], qf[t][0], qf[t][1], qf[t][2], qf[t][3], b0, b1);
            }
        }

        const float scale = 0.125f;
        bool diag = (ti >= NT - 2);
        int grow0 = m0 + wid*16 + g;
        int grow1 = grow0 + 8;
        float mx0 = -1e30f, mx1 = -1e30f;
        #pragma unroll
        for (int nt = 0; nt < 8; nt++) {
            int c0 = ti*64 + nt*8 + 2*i4;
            float v0 = s[nt][0]*scale, v1 = s[nt][1]*scale;
            float v2 = s[nt][2]*scale, v3 = s[nt][3]*scale;
            if (diag) {
                if (c0     > grow0) v0 = -1e30f;
                if (c0 + 1 > grow0) v1 = -1e30f;
                if (c0     > grow1) v2 = -1e30f;
                if (c0 + 1 > grow1) v3 = -1e30f;
            }
            s[nt][0]=v0; s[nt][1]=v1; s[nt][2]=v2; s[nt][3]=v3;
            mx0 = fmaxf(mx0, fmaxf(v0, v1));
            mx1 = fmaxf(mx1, fmaxf(v2, v3));
        }
        mx0 = fmaxf(mx0, __shfl_xor_sync(0xffffffffu, mx0, 1));
        mx0 = fmaxf(mx0, __shfl_xor_sync(0xffffffffu, mx0, 2));
        mx1 = fmaxf(mx1, __shfl_xor_sync(0xffffffffu, mx1, 1));
        mx1 = fmaxf(mx1, __shfl_xor_sync(0xffffffffu, mx1, 2));
        float nm0 = fmaxf(m0f, mx0), nm1 = fmaxf(m1f, mx1);
        float a0 = __expf(m0f - nm0), a1 = __expf(m1f - nm1);
        float sum0 = 0.f, sum1 = 0.f;
        #pragma unroll
        for (int nt = 0; nt < 8; nt++) {
            float p0 = __expf(s[nt][0] - nm0);
            float p1 = __expf(s[nt][1] - nm0);
            float p2 = __expf(s[nt][2] - nm1);
            float p3 = __expf(s[nt][3] - nm1);
            s[nt][0]=p0; s[nt][1]=p1; s[nt][2]=p2; s[nt][3]=p3;
            sum0 += p0 + p1; sum1 += p2 + p3;
        }
        sum0 += __shfl_xor_sync(0xffffffffu, sum0, 1);
        sum0 += __shfl_xor_sync(0xffffffffu, sum0, 2);
        sum1 += __shfl_xor_sync(0xffffffffu, sum1, 1);
        sum1 += __shfl_xor_sync(0xffffffffu, sum1, 2);
        l0f = l0f * a0 + sum0; l1f = l1f * a1 + sum1;
        m0f = nm0; m1f = nm1;
        #pragma unroll
        for (int u = 0; u < 8; u++) {
            o[u][0] *= a0; o[u][1] *= a0; o[u][2] *= a1; o[u][3] *= a1;
        }

        // O += P V
        #pragma unroll
        for (int t = 0; t < 4; t++) {
            uint32_t pa0 = packh(s[2*t][0],   s[2*t][1]);
            uint32_t pa1 = packh(s[2*t][2],   s[2*t][3]);
            uint32_t pa2 = packh(s[2*t+1][0], s[2*t+1][1]);
            uint32_t pa3 = packh(s[2*t+1][2], s[2*t+1][3]);
            #pragma unroll
            for (int u = 0; u < 4; u++) {
                uint32_t addr = sV + (uint32_t)((t*16 + (lane & 15))*36
                                                + u*8 + ((lane >> 4) << 2))*4;
                uint32_t r0, r1, r2, r3;
                ldmx4t(r0, r1, r2, r3, addr);
                mma16816(o[2*u],     pa0, pa1, pa2, pa3, r0, r1);
                mma16816(o[2*u + 1], pa0, pa1, pa2, pa3, r2, r3);
            }
        }
        __syncthreads();
    }

    // epilogue: merged heads, fp16
    float inv0 = 1.f / l0f, inv1 = 1.f / l1f;
    int r0g = m0 + wid*16 + g;
    size_t base0 = ((size_t)b * SS + r0g) * DD + h * DHD;
    size_t base1 = base0 + 8 * (size_t)DD;
    #pragma unroll
    for (int u = 0; u < 8; u++) {
        int col = u*8 + 2*i4;
        *(uint32_t*)(O16 + base0 + col) = packh(o[u][0]*inv0, o[u][1]*inv0);
        *(uint32_t*)(O16 + base1 + col) = packh(o[u][2]*inv1, o[u][3]*inv1);
    }
}

// ---------------- host launcher ----------------
extern "C" void kernel_launch(void* const* d_in, const int* in_sizes, int n_in,
                              void* d_out, int out_size) {
    const float* hidden = (const float*)d_in[0];
    const float* ln1_g  = (const float*)d_in[1];
    const float* ln1_b  = (const float*)d_in[2];
    const float* ln2_g  = (const float*)d_in[3];
    const float* ln2_b  = (const float*)d_in[4];
    const float* q_U = (const float*)d_in[5];
    const float* q_V = (const float*)d_in[6];
    const float* q_b = (const float*)d_in[7];
    const float* k_U = (const float*)d_in[8];
    const float* k_V = (const float*)d_in[9];
    const float* k_b = (const float*)d_in[10];
    const float* v_U = (const float*)d_in[11];
    const float* v_V = (const float*)d_in[12];
    const float* v_b = (const float*)d_in[13];
    const float* out_U = (const float*)d_in[14];
    const float* out_V = (const float*)d_in[15];
    const float* out_b = (const float*)d_in[16];
    const float* fc1_U = (const float*)d_in[17];
    const float* fc1_V = (const float*)d_in[18];
    const float* fc1_b = (const float*)d_in[19];
    const float* fc2_U = (const float*)d_in[20];
    const float* fc2_V = (const float*)d_in[21];
    const float* fc2_b = (const float*)d_in[22];
    float* out = (float*)d_out;

    float *QKVr, *hb;
    __half *A16, *C16, *Q16, *K16, *V16;
    __half *Wqkv, *Wou, *Wov, *Wf1u, *Wf1v, *Wf2u, *Wf2v;
    cudaGetSymbolAddress((void**)&QKVr, g_QKVr);
    cudaGetSymbolAddress((void**)&hb,   g_h);
    cudaGetSymbolAddress((void**)&A16,  g_A16);
    cudaGetSymbolAddress((void**)&C16,  g_C16);
    cudaGetSymbolAddress((void**)&Q16,  g_Q16);
    cudaGetSymbolAddress((void**)&K16,  g_K16);
    cudaGetSymbolAddress((void**)&V16,  g_V16);
    cudaGetSymbolAddress((void**)&Wqkv, g_Wqkv);
    cudaGetSymbolAddress((void**)&Wou,  g_Wou);
    cudaGetSymbolAddress((void**)&Wov,  g_Wov);
    cudaGetSymbolAddress((void**)&Wf1u, g_Wf1u);
    cudaGetSymbolAddress((void**)&Wf1v, g_Wf1v);
    cudaGetSymbolAddress((void**)&Wf2u, g_Wf2u);
    cudaGetSymbolAddress((void**)&Wf2v, g_Wf2v);

    cudaFuncSetAttribute(gemm_mma<0,0>, cudaFuncAttributeMaxDynamicSharedMemorySize, GM_SMEM);
    cudaFuncSetAttribute(gemm_mma<0,1>, cudaFuncAttributeMaxDynamicSharedMemorySize, GM_SMEM);
    cudaFuncSetAttribute(gemm_mma<1,0>, cudaFuncAttributeMaxDynamicSharedMemorySize, GM_SMEM);
    cudaFuncSetAttribute(gemm_mma<2,1>, cudaFuncAttributeMaxDynamicSharedMemorySize, GM_SMEM);
    cudaFuncSetAttribute(flash_mma, cudaFuncAttributeMaxDynamicSharedMemorySize, FA_SMEM);

    dim3 wblk(32, 8);
    convW<<<dim3(HR/32, DD/32), wblk>>>(q_U, Wqkv,           DD, HR);
    convW<<<dim3(HR/32, DD/32), wblk>>>(k_U, Wqkv + HR*DD,   DD, HR);
    convW<<<dim3(HR/32, DD/32), wblk>>>(v_U, Wqkv + 2*HR*DD, DD, HR);
    convW<<<dim3(R_OUT/32, DD/32), wblk>>>(out_U, Wou, DD, R_OUT);
    convW<<<dim3(DD/32, R_OUT/32), wblk>>>(out_V, Wov, R_OUT, DD);
    convW<<<dim3(R_FC/32, DD/32), wblk>>>(fc1_U, Wf1u, DD, R_FC);
    convW<<<dim3(II/32, R_FC/32), wblk>>>(fc1_V, Wf1v, R_FC, II);
    convW<<<dim3(R_FC/32, II/32), wblk>>>(fc2_U, Wf2u, II, R_FC);
    convW<<<dim3(DD/32, R_FC/32), wblk>>>(fc2_V, Wf2v, R_FC, DD);

    // 1. LN1 -> fp16
    ln_half<<<NROW, 256>>>(hidden, A16, ln1_g, ln1_b);
    // 2. fused qkv rank projection -> fp32 [4096, 1536]
    gemm_mma<0,0><<<dim3(HR3/128, NROW/128), 256, GM_SMEM>>>(A16, Wqkv, QKVr, nullptr,
        nullptr, nullptr, NROW, HR3, DD);
    // 3. per-head expansion (q,k,v fused via grid.z)
    expand3<<<dim3(SS/64, BB*HH, 3), 256>>>(QKVr, q_V, k_V, v_V, q_b, k_b, v_b,
                                            Q16, K16, V16);
    // 4. flash attention -> merged-head fp16 Y in C16
    flash_mma<<<dim3(SS/128, BB*HH), 256, FA_SMEM>>>(Q16, K16, V16, C16);
    // 5. out projection + residual
    gemm_mma<0,1><<<dim3(R_OUT/128, NROW/128), 256, GM_SMEM>>>(C16, Wou, nullptr, A16,
        nullptr, nullptr, NROW, R_OUT, DD);
    gemm_mma<1,0><<<dim3(DD/128, NROW/128), 256, GM_SMEM>>>(A16, Wov, hb, nullptr,
        out_b, hidden, NROW, DD, R_OUT);
    // 6. LN2 -> fp16
    ln_half<<<NROW, 256>>>(hb, C16, ln2_g, ln2_b);
    // 7. MLP
    gemm_mma<0,1><<<dim3(R_FC/128, NROW/128), 256, GM_SMEM>>>(C16, Wf1u, nullptr, A16,
        nullptr, nullptr, NROW, R_FC, DD);
    gemm_mma<2,1><<<dim3(II/128, NROW/128), 256, GM_SMEM>>>(A16, Wf1v, nullptr, C16,
        fc1_b, nullptr, NROW, II, R_FC);
    gemm_mma<0,1><<<dim3(R_FC/128, NROW/128), 256, GM_SMEM>>>(C16, Wf2u, nullptr, A16,
        nullptr, nullptr, NROW, R_FC, II);
    gemm_mma<1,0><<<dim3(DD/128, NROW/128), 256, GM_SMEM>>>(A16, Wf2v, out, nullptr,
        fc2_b, hb, NROW, DD, R_FC);
}

// round 6
// speedup vs baseline: 7.0572x; 1.1024x over previous
#include <cuda_runtime.h>
#include <cuda_fp16.h>
#include <math.h>
#include <stdint.h>

// ---------------- problem constants ----------------
#define BB 2
#define SS 2048
#define DD 1024
#define HH 16
#define DHD 64
#define NROW (BB*SS)      // 4096
#define RA 32
#define HR 512
#define HR3 1536
#define R_OUT 512
#define II 4096
#define R_FC 512

// ---------------- device scratch ----------------
__device__ float g_h[NROW*DD];

__device__ __align__(1024) __half g_R16[NROW*HR3];   // qkv rank coeffs fp16
__device__ __align__(1024) __half g_Q16[NROW*DD];
__device__ __align__(1024) __half g_K16[NROW*DD];
__device__ __align__(1024) __half g_V16[NROW*DD];

__device__ __align__(1024) __half g_A16[NROW*DD];
__device__ __align__(1024) __half g_C16[NROW*II];

__device__ __align__(1024) __half g_Wqkv[HR3*DD];
__device__ __align__(1024) __half g_Wou [R_OUT*DD];
__device__ __align__(1024) __half g_Wov [DD*R_OUT];
__device__ __align__(1024) __half g_Wf1u[R_FC*DD];
__device__ __align__(1024) __half g_Wf1v[II*R_FC];
__device__ __align__(1024) __half g_Wf2u[R_FC*II];
__device__ __align__(1024) __half g_Wf2v[DD*R_FC];

// ================= low-level helpers =================
__device__ __forceinline__ uint32_t smem_u32(const void* p) {
    uint32_t a;
    asm("{ .reg .u64 t; cvta.to.shared.u64 t, %1; cvt.u32.u64 %0, t; }" : "=r"(a) : "l"(p));
    return a;
}
__device__ __forceinline__ void cpa16(uint32_t dst, const void* src) {
    asm volatile("cp.async.cg.shared.global [%0], [%1], 16;" :: "r"(dst), "l"(src) : "memory");
}
#define CP_COMMIT() asm volatile("cp.async.commit_group;" ::: "memory")
#define CP_WAIT(n)  asm volatile("cp.async.wait_group %0;" :: "n"(n) : "memory")

__device__ __forceinline__ void mma16816(float* c, uint32_t a0, uint32_t a1, uint32_t a2,
                                         uint32_t a3, uint32_t b0, uint32_t b1) {
    asm volatile(
        "mma.sync.aligned.m16n8k16.row.col.f32.f16.f16.f32 "
        "{%0,%1,%2,%3}, {%4,%5,%6,%7}, {%8,%9}, {%0,%1,%2,%3};"
        : "+f"(c[0]), "+f"(c[1]), "+f"(c[2]), "+f"(c[3])
        : "r"(a0), "r"(a1), "r"(a2), "r"(a3), "r"(b0), "r"(b1));
}
__device__ __forceinline__ void ldmx4(uint32_t& r0, uint32_t& r1, uint32_t& r2,
                                      uint32_t& r3, uint32_t addr) {
    asm volatile("ldmatrix.sync.aligned.m8n8.x4.shared.b16 {%0,%1,%2,%3}, [%4];"
                 : "=r"(r0), "=r"(r1), "=r"(r2), "=r"(r3) : "r"(addr));
}
__device__ __forceinline__ void ldmx4t(uint32_t& r0, uint32_t& r1, uint32_t& r2,
                                       uint32_t& r3, uint32_t addr) {
    asm volatile("ldmatrix.sync.aligned.m8n8.x4.trans.shared.b16 {%0,%1,%2,%3}, [%4];"
                 : "=r"(r0), "=r"(r1), "=r"(r2), "=r"(r3) : "r"(addr));
}
__device__ __forceinline__ uint32_t packh(float a, float b) {
    __half2 t = __float22half2_rn(make_float2(a, b));
    return *(uint32_t*)&t;
}

// ---------------- ALL weight transposes+converts in ONE kernel ----------------
// 7680 tiles of 32x32: [0,1536) qkv | [1536,2048) out_U | [2048,2560) out_V |
// [2560,3072) fc1_U | [3072,5120) fc1_V | [5120,7168) fc2_U | [7168,7680) fc2_V
__global__ void convAll(const float* __restrict__ q_U, const float* __restrict__ k_U,
                        const float* __restrict__ v_U, const float* __restrict__ out_U,
                        const float* __restrict__ out_V, const float* __restrict__ fc1_U,
                        const float* __restrict__ fc1_V, const float* __restrict__ fc2_U,
                        const float* __restrict__ fc2_V,
                        __half* Wqkv, __half* Wou, __half* Wov, __half* Wf1u,
                        __half* Wf1v, __half* Wf2u, __half* Wf2v) {
    int bid = blockIdx.x;
    const float* src; __half* dst; int K, N, local;
    if (bid < 1536) {
        int s = bid >> 9; local = bid & 511;
        src = (s == 0) ? q_U : (s == 1) ? k_U : v_U;
        dst = Wqkv + (size_t)s * HR * DD; K = DD; N = HR;
    } else if (bid < 2048) { local = bid - 1536; src = out_U; dst = Wou;  K = DD;    N = R_OUT; }
    else if (bid < 2560)   { local = bid - 2048; src = out_V; dst = Wov;  K = R_OUT; N = DD; }
    else if (bid < 3072)   { local = bid - 2560; src = fc1_U; dst = Wf1u; K = DD;    N = R_FC; }
    else if (bid < 5120)   { local = bid - 3072; src = fc1_V; dst = Wf1v; K = R_FC;  N = II; }
    else if (bid < 7168)   { local = bid - 5120; src = fc2_U; dst = Wf2u; K = II;    N = R_FC; }
    else                   { local = bid - 7168; src = fc2_V; dst = Wf2v; K = R_FC;  N = DD; }
    int nx = N >> 5;
    int n0 = (local % nx) << 5, k0 = (local / nx) << 5;

    __shared__ float t[32][33];
    int tx = threadIdx.x, ty = threadIdx.y;  // 32x8
    #pragma unroll
    for (int i = 0; i < 4; i++)
        t[ty + 8*i][tx] = src[(size_t)(k0 + ty + 8*i) * N + n0 + tx];
    __syncthreads();
    #pragma unroll
    for (int i = 0; i < 4; i++)
        dst[(size_t)(n0 + ty + 8*i) * K + k0 + tx] = __float2half(t[tx][ty + 8*i]);
}

// ---------------- fp16 GEMM, ldmatrix + 3-stage cp.async ----------------
// C[M,N] = A[M,K] @ B[N,K]^T ; 128x128 tile, BK=32, 8 warps (2x4).
// EPI: 0=none, 1=bias+residual, 2=bias+GELU ; OUT: 0=fp32, 1=fp16
#define PAD_W 40
#define MAT_B (128*PAD_W*2)   // 10240
#define STG_B (2*MAT_B)       // 20480
#define NSTG 3
#define GM_SMEM (NSTG*STG_B)  // 61440

__device__ __forceinline__ void copy_stage(uint32_t sst,
        const __half* __restrict__ Ap, const __half* __restrict__ Bp,
        int K, int k0, int tid) {
    #pragma unroll
    for (int it = 0; it < 2; it++) {
        int i = tid + it * 256;
        int row = i >> 2, q = i & 3;
        size_t go = (size_t)row * K + k0 + q * 8;
        uint32_t so = (uint32_t)(row * PAD_W + q * 8) * 2;
        cpa16(sst + so,         Ap + go);
        cpa16(sst + MAT_B + so, Bp + go);
    }
}

template<int EPI, int OUT>
__global__ void __launch_bounds__(256, 2)
gemm_mma(const __half* __restrict__ A, const __half* __restrict__ B,
         float* __restrict__ C, __half* __restrict__ O16,
         const float* __restrict__ bias, const float* __restrict__ res,
         int M, int N, int K) {
    extern __shared__ char smem_raw[];
    uint32_t sbase = smem_u32(smem_raw);
    int tid = threadIdx.x;
    int wid = tid >> 5, lane = tid & 31;
    int wm = wid >> 2, wn = wid & 3;
    int g = lane >> 2, i4 = lane & 3;
    int bm = blockIdx.y * 128, bn = blockIdx.x * 128;

    const __half* Ap = A + (size_t)bm * K;
    const __half* Bp = B + (size_t)bn * K;

    float acc[4][4][4];
    #pragma unroll
    for (int a = 0; a < 4; a++)
        #pragma unroll
        for (int b = 0; b < 4; b++)
            #pragma unroll
            for (int c = 0; c < 4; c++) acc[a][b][c] = 0.f;

    // per-thread ldmatrix address components
    int arow = wm * 64 + (lane & 15);
    int acol0 = (lane >> 4) * 8;
    int brow = wn * 32 + (lane & 7) + ((lane >> 4) << 3);
    int bcol0 = ((lane >> 3) & 1) * 8;

    int NC = K >> 5;
    copy_stage(sbase, Ap, Bp, K, 0, tid);
    CP_COMMIT();
    copy_stage(sbase + STG_B, Ap, Bp, K, 32, tid);
    CP_COMMIT();

    for (int c = 0; c < NC; c++) {
        if (c == NC - 1) { CP_WAIT(0); } else { CP_WAIT(1); }
        __syncthreads();

        uint32_t st = sbase + (uint32_t)(c % NSTG) * STG_B;
        uint32_t stA = st, stB = st + MAT_B;

        #pragma unroll
        for (int ks = 0; ks < 2; ks++) {
            uint32_t bf[4][2];
            #pragma unroll
            for (int nip = 0; nip < 2; nip++) {
                uint32_t addr = stB + (uint32_t)((brow + nip * 16) * PAD_W
                                                 + ks * 16 + bcol0) * 2;
                ldmx4(bf[2*nip][0], bf[2*nip][1], bf[2*nip+1][0], bf[2*nip+1][1], addr);
            }
            #pragma unroll
            for (int mi = 0; mi < 4; mi++) {
                uint32_t addr = stA + (uint32_t)((arow + mi * 16) * PAD_W
                                                 + ks * 16 + acol0) * 2;
                uint32_t a0, a1, a2, a3;
                ldmx4(a0, a1, a2, a3, addr);
                #pragma unroll
                for (int ni = 0; ni < 4; ni++)
                    mma16816(acc[mi][ni], a0, a1, a2, a3, bf[ni][0], bf[ni][1]);
            }
        }
        __syncthreads();
        if (c + 2 < NC) {
            copy_stage(sbase + (uint32_t)((c + 2) % NSTG) * STG_B, Ap, Bp, K, (c + 2) << 5, tid);
            CP_COMMIT();
        }
    }

    #pragma unroll
    for (int mi = 0; mi < 4; mi++) {
        int row0 = bm + wm * 64 + mi * 16 + g;
        #pragma unroll
        for (int ni = 0; ni < 4; ni++) {
            int col = bn + wn * 32 + ni * 8 + i4 * 2;
            float v[4];
            v[0] = acc[mi][ni][0]; v[1] = acc[mi][ni][1];
            v[2] = acc[mi][ni][2]; v[3] = acc[mi][ni][3];
            if (EPI != 0) {
                float b0 = bias[col], b1 = bias[col + 1];
                v[0] += b0; v[1] += b1; v[2] += b0; v[3] += b1;
            }
            if (EPI == 2) {
                #pragma unroll
                for (int t = 0; t < 4; t++)
                    v[t] = 0.5f * v[t] * (1.0f + erff(v[t] * 0.70710678118654752f));
            }
            if (EPI == 1) {
                const float* r0 = res + (size_t)row0 * N + col;
                const float* r1 = r0 + 8 * (size_t)N;
                v[0] += r0[0]; v[1] += r0[1]; v[2] += r1[0]; v[3] += r1[1];
            }
            if (OUT == 0) {
                float* p0 = C + (size_t)row0 * N + col;
                float* p1 = p0 + 8 * (size_t)N;
                *(float2*)p0 = make_float2(v[0], v[1]);
                *(float2*)p1 = make_float2(v[2], v[3]);
            } else {
                size_t o0 = (size_t)row0 * N + col;
                size_t o1 = o0 + 8 * (size_t)N;
                *(uint32_t*)(O16 + o0) = packh(v[0], v[1]);
                *(uint32_t*)(O16 + o1) = packh(v[2], v[3]);
            }
        }
    }
}

// ---------------- layernorm with fp16 output ----------------
__global__ void ln_half(const float* __restrict__ in, __half* __restrict__ out,
                        const float* __restrict__ gw, const float* __restrict__ bw) {
    int row = blockIdx.x;
    int tid = threadIdx.x;
    const float4* x4 = (const float4*)(in + (size_t)row * DD);
    float4 v = x4[tid];
    __shared__ float red[8];
    __shared__ float stat[2];
    float s = v.x + v.y + v.z + v.w;
    #pragma unroll
    for (int o = 16; o; o >>= 1) s += __shfl_xor_sync(0xffffffffu, s, o);
    if ((tid & 31) == 0) red[tid >> 5] = s;
    __syncthreads();
    if (tid < 32) {
        float t = (tid < 8) ? red[tid] : 0.f;
        #pragma unroll
        for (int o = 4; o; o >>= 1) t += __shfl_xor_sync(0xffffffffu, t, o);
        if (tid == 0) stat[0] = t * (1.0f / DD);
    }
    __syncthreads();
    float mu = stat[0];
    float a = v.x - mu, b = v.y - mu, c = v.z - mu, d = v.w - mu;
    float s2 = a*a + b*b + c*c + d*d;
    #pragma unroll
    for (int o = 16; o; o >>= 1) s2 += __shfl_xor_sync(0xffffffffu, s2, o);
    if ((tid & 31) == 0) red[tid >> 5] = s2;
    __syncthreads();
    if (tid < 32) {
        float t = (tid < 8) ? red[tid] : 0.f;
        #pragma unroll
        for (int o = 4; o; o >>= 1) t += __shfl_xor_sync(0xffffffffu, t, o);
        if (tid == 0) stat[1] = rsqrtf(t * (1.0f / DD) + 1e-5f);
    }
    __syncthreads();
    float rs = stat[1];
    float4 g4 = ((const float4*)gw)[tid];
    float4 b4 = ((const float4*)bw)[tid];
    size_t base = (size_t)row * DD + tid * 4;
    *(uint32_t*)(out + base)     = packh(a*rs*g4.x + b4.x, b*rs*g4.y + b4.y);
    *(uint32_t*)(out + base + 2) = packh(c*rs*g4.z + b4.z, d*rs*g4.w + b4.w);
}

// ---------------- fused per-head rank expansion (fp16 in, fp16 out) --------
__global__ void expand3(const __half* __restrict__ Xr,
                        const float* __restrict__ qV, const float* __restrict__ kV,
                        const float* __restrict__ vV, const float* __restrict__ qb,
                        const float* __restrict__ kb, const float* __restrict__ vb,
                        __half* __restrict__ Qo, __half* __restrict__ Ko,
                        __half* __restrict__ Vo) {
    int which = blockIdx.z;
    const float* Vh = (which == 0) ? qV : (which == 1) ? kV : vV;
    const float* bias = (which == 0) ? qb : (which == 1) ? kb : vb;
    __half* out = (which == 0) ? Qo : (which == 1) ? Ko : Vo;
    const __half* X = Xr + which * HR;

    int bh = blockIdx.y;
    int b  = bh / HH;
    int h  = bh % HH;
    int s0 = blockIdx.x * 64;
    __shared__ float Vs[RA][DHD];
    __shared__ float Xs[64][RA];
    int tid = threadIdx.x;
    const float* vp = Vh + (size_t)h * RA * DHD;
    for (int i = tid; i < RA * DHD / 4; i += 256)
        ((float4*)Vs)[i] = ((const float4*)vp)[i];
    for (int i = tid; i < 64 * RA / 4; i += 256) {
        int r = i >> 3, c4 = (i & 7) << 2;
        const __half2* xp = (const __half2*)(X + (size_t)(b * SS + s0 + r) * HR3 + h * RA + c4);
        float2 f0 = __half22float2(xp[0]);
        float2 f1 = __half22float2(xp[1]);
        Xs[r][c4]   = f0.x; Xs[r][c4+1] = f0.y;
        Xs[r][c4+2] = f1.x; Xs[r][c4+3] = f1.y;
    }
    __syncthreads();
    for (int i = tid; i < 64 * DHD; i += 256) {
        int sl = i >> 6, e = i & 63;
        float acc = bias[h * DHD + e];
        #pragma unroll
        for (int r = 0; r < RA; r++) acc = fmaf(Xs[sl][r], Vs[r][e], acc);
        out[((size_t)bh * SS + s0 + sl) * DHD + e] = __float2half(acc);
    }
}

// ---------------- flash attention, fp16 mma + ldmatrix, 128-row Q tile ------
#define FA_SMEM ((128*72 + 2*2*64*72) * 2)   // 55296 bytes
__global__ void __launch_bounds__(256)
flash_mma(const __half* __restrict__ Qg_, const __half* __restrict__ Kg_,
          const __half* __restrict__ Vg_, __half* __restrict__ O16) {
    extern __shared__ char fsm[];
    uint32_t sQ = smem_u32(fsm);
    uint32_t sKV = sQ + 128*72*2;
    const uint32_t VOFF = 64*72*2;
    const uint32_t STGB = 2*VOFF;
    int bh = blockIdx.y;
    int b = bh >> 4, h = bh & 15;
    int m0 = ((int)gridDim.x - 1 - (int)blockIdx.x) * 128;
    int tid = threadIdx.x, wid = tid >> 5, lane = tid & 31;
    int g = lane >> 2, i4 = lane & 3;
    const __half* Qg = Qg_ + ((size_t)bh * SS + m0) * DHD;
    const __half* Kg = Kg_ + (size_t)bh * SS * DHD;
    const __half* Vg = Vg_ + (size_t)bh * SS * DHD;

    #pragma unroll
    for (int it = 0; it < 4; it++) {
        int i = tid + it * 256; int r = i >> 3, q = i & 7;
        cpa16(sQ + (uint32_t)(r*72 + q*8)*2, Qg + (size_t)r*DHD + q*8);
    }
    CP_COMMIT();
    #pragma unroll
    for (int it = 0; it < 2; it++) {
        int i = tid + it * 256; int r = i >> 3, q = i & 7;
        uint32_t so = (uint32_t)(r*72 + q*8)*2;
        cpa16(sKV + so,        Kg + (size_t)r*DHD + q*8);
        cpa16(sKV + VOFF + so, Vg + (size_t)r*DHD + q*8);
    }
    CP_COMMIT();
    CP_WAIT(1);
    __syncthreads();

    // Q fragments via ldmatrix
    uint32_t qf[4][4];
    {
        uint32_t base = sQ + (uint32_t)((wid*16 + (lane & 15))*72 + (lane >> 4)*8)*2;
        #pragma unroll
        for (int t = 0; t < 4; t++)
            ldmx4(qf[t][0], qf[t][1], qf[t][2], qf[t][3], base + (uint32_t)(t*16)*2);
    }

    float o[8][4];
    #pragma unroll
    for (int u = 0; u < 8; u++) { o[u][0]=o[u][1]=o[u][2]=o[u][3]=0.f; }
    float m0f = -1e30f, m1f = -1e30f, l0f = 0.f, l1f = 0.f;

    int kbrow = (lane & 7) + ((lane >> 4) << 3);
    int kbcol = ((lane >> 3) & 1) * 8;

    int NT = m0/64 + 2;
    for (int ti = 0; ti < NT; ti++) {
        if (ti + 1 < NT) {
            const __half* Kp = Kg + (size_t)(ti+1)*64*DHD;
            const __half* Vp = Vg + (size_t)(ti+1)*64*DHD;
            uint32_t sst = sKV + ((uint32_t)(ti+1) & 1) * STGB;
            #pragma unroll
            for (int it = 0; it < 2; it++) {
                int i = tid + it * 256; int r = i >> 3, q = i & 7;
                uint32_t so = (uint32_t)(r*72 + q*8)*2;
                cpa16(sst + so,        Kp + (size_t)r*DHD + q*8);
                cpa16(sst + VOFF + so, Vp + (size_t)r*DHD + q*8);
            }
            CP_COMMIT();
            CP_WAIT(1);
        } else {
            CP_WAIT(0);
        }
        __syncthreads();
        uint32_t sK = sKV + ((uint32_t)ti & 1) * STGB;
        uint32_t sV = sK + VOFF;

        // S = Q K^T  (K fragments via ldmatrix.x4, 2 nt per load)
        float s[8][4];
        #pragma unroll
        for (int nt = 0; nt < 8; nt++) { s[nt][0]=s[nt][1]=s[nt][2]=s[nt][3]=0.f; }
        #pragma unroll
        for (int t = 0; t < 4; t++) {
            #pragma unroll
            for (int nip = 0; nip < 4; nip++) {
                uint32_t addr = sK + (uint32_t)((nip*16 + kbrow)*72 + t*16 + kbcol)*2;
                uint32_t b0, b1, b2, b3;
                ldmx4(b0, b1, b2, b3, addr);
                mma16816(s[2*nip],   qf[t][0], qf[t][1], qf[t][2], qf[t][3], b0, b1);
                mma16816(s[2*nip+1], qf[t][0], qf[t][1], qf[t][2], qf[t][3], b2, b3);
            }
        }

        const float scale = 0.125f;
        bool diag = (ti >= NT - 2);
        int grow0 = m0 + wid*16 + g;
        int grow1 = grow0 + 8;
        float mx0 = -1e30f, mx1 = -1e30f;
        #pragma unroll
        for (int nt = 0; nt < 8; nt++) {
            int c0 = ti*64 + nt*8 + 2*i4;
            float v0 = s[nt][0]*scale, v1 = s[nt][1]*scale;
            float v2 = s[nt][2]*scale, v3 = s[nt][3]*scale;
            if (diag) {
                if (c0     > grow0) v0 = -1e30f;
                if (c0 + 1 > grow0) v1 = -1e30f;
                if (c0     > grow1) v2 = -1e30f;
                if (c0 + 1 > grow1) v3 = -1e30f;
            }
            s[nt][0]=v0; s[nt][1]=v1; s[nt][2]=v2; s[nt][3]=v3;
            mx0 = fmaxf(mx0, fmaxf(v0, v1));
            mx1 = fmaxf(mx1, fmaxf(v2, v3));
        }
        mx0 = fmaxf(mx0, __shfl_xor_sync(0xffffffffu, mx0, 1));
        mx0 = fmaxf(mx0, __shfl_xor_sync(0xffffffffu, mx0, 2));
        mx1 = fmaxf(mx1, __shfl_xor_sync(0xffffffffu, mx1, 1));
        mx1 = fmaxf(mx1, __shfl_xor_sync(0xffffffffu, mx1, 2));
        float nm0 = fmaxf(m0f, mx0), nm1 = fmaxf(m1f, mx1);
        float a0 = __expf(m0f - nm0), a1 = __expf(m1f - nm1);
        float sum0 = 0.f, sum1 = 0.f;
        #pragma unroll
        for (int nt = 0; nt < 8; nt++) {
            float p0 = __expf(s[nt][0] - nm0);
            float p1 = __expf(s[nt][1] - nm0);
            float p2 = __expf(s[nt][2] - nm1);
            float p3 = __expf(s[nt][3] - nm1);
            s[nt][0]=p0; s[nt][1]=p1; s[nt][2]=p2; s[nt][3]=p3;
            sum0 += p0 + p1; sum1 += p2 + p3;
        }
        sum0 += __shfl_xor_sync(0xffffffffu, sum0, 1);
        sum0 += __shfl_xor_sync(0xffffffffu, sum0, 2);
        sum1 += __shfl_xor_sync(0xffffffffu, sum1, 1);
        sum1 += __shfl_xor_sync(0xffffffffu, sum1, 2);
        l0f = l0f * a0 + sum0; l1f = l1f * a1 + sum1;
        m0f = nm0; m1f = nm1;
        #pragma unroll
        for (int u = 0; u < 8; u++) {
            o[u][0] *= a0; o[u][1] *= a0; o[u][2] *= a1; o[u][3] *= a1;
        }

        // O += P V
        #pragma unroll
        for (int t = 0; t < 4; t++) {
            uint32_t pa0 = packh(s[2*t][0],   s[2*t][1]);
            uint32_t pa1 = packh(s[2*t][2],   s[2*t][3]);
            uint32_t pa2 = packh(s[2*t+1][0], s[2*t+1][1]);
            uint32_t pa3 = packh(s[2*t+1][2], s[2*t+1][3]);
            #pragma unroll
            for (int u = 0; u < 4; u++) {
                uint32_t addr = sV + (uint32_t)((t*16 + (lane & 15))*36
                                                + u*8 + ((lane >> 4) << 2))*4;
                uint32_t r0, r1, r2, r3;
                ldmx4t(r0, r1, r2, r3, addr);
                mma16816(o[2*u],     pa0, pa1, pa2, pa3, r0, r1);
                mma16816(o[2*u + 1], pa0, pa1, pa2, pa3, r2, r3);
            }
        }
        __syncthreads();
    }

    float inv0 = 1.f / l0f, inv1 = 1.f / l1f;
    int r0g = m0 + wid*16 + g;
    size_t base0 = ((size_t)b * SS + r0g) * DD + h * DHD;
    size_t base1 = base0 + 8 * (size_t)DD;
    #pragma unroll
    for (int u = 0; u < 8; u++) {
        int col = u*8 + 2*i4;
        *(uint32_t*)(O16 + base0 + col) = packh(o[u][0]*inv0, o[u][1]*inv0);
        *(uint32_t*)(O16 + base1 + col) = packh(o[u][2]*inv1, o[u][3]*inv1);
    }
}

// ---------------- host launcher ----------------
extern "C" void kernel_launch(void* const* d_in, const int* in_sizes, int n_in,
                              void* d_out, int out_size) {
    const float* hidden = (const float*)d_in[0];
    const float* ln1_g  = (const float*)d_in[1];
    const float* ln1_b  = (const float*)d_in[2];
    const float* ln2_g  = (const float*)d_in[3];
    const float* ln2_b  = (const float*)d_in[4];
    const float* q_U = (const float*)d_in[5];
    const float* q_V = (const float*)d_in[6];
    const float* q_b = (const float*)d_in[7];
    const float* k_U = (const float*)d_in[8];
    const float* k_V = (const float*)d_in[9];
    const float* k_b = (const float*)d_in[10];
    const float* v_U = (const float*)d_in[11];
    const float* v_V = (const float*)d_in[12];
    const float* v_b = (const float*)d_in[13];
    const float* out_U = (const float*)d_in[14];
    const float* out_V = (const float*)d_in[15];
    const float* out_b = (const float*)d_in[16];
    const float* fc1_U = (const float*)d_in[17];
    const float* fc1_V = (const float*)d_in[18];
    const float* fc1_b = (const float*)d_in[19];
    const float* fc2_U = (const float*)d_in[20];
    const float* fc2_V = (const float*)d_in[21];
    const float* fc2_b = (const float*)d_in[22];
    float* out = (float*)d_out;

    float* hb;
    __half *A16, *C16, *R16, *Q16, *K16, *V16;
    __half *Wqkv, *Wou, *Wov, *Wf1u, *Wf1v, *Wf2u, *Wf2v;
    cudaGetSymbolAddress((void**)&hb,   g_h);
    cudaGetSymbolAddress((void**)&A16,  g_A16);
    cudaGetSymbolAddress((void**)&C16,  g_C16);
    cudaGetSymbolAddress((void**)&R16,  g_R16);
    cudaGetSymbolAddress((void**)&Q16,  g_Q16);
    cudaGetSymbolAddress((void**)&K16,  g_K16);
    cudaGetSymbolAddress((void**)&V16,  g_V16);
    cudaGetSymbolAddress((void**)&Wqkv, g_Wqkv);
    cudaGetSymbolAddress((void**)&Wou,  g_Wou);
    cudaGetSymbolAddress((void**)&Wov,  g_Wov);
    cudaGetSymbolAddress((void**)&Wf1u, g_Wf1u);
    cudaGetSymbolAddress((void**)&Wf1v, g_Wf1v);
    cudaGetSymbolAddress((void**)&Wf2u, g_Wf2u);
    cudaGetSymbolAddress((void**)&Wf2v, g_Wf2v);

    cudaFuncSetAttribute(gemm_mma<0,0>, cudaFuncAttributeMaxDynamicSharedMemorySize, GM_SMEM);
    cudaFuncSetAttribute(gemm_mma<0,1>, cudaFuncAttributeMaxDynamicSharedMemorySize, GM_SMEM);
    cudaFuncSetAttribute(gemm_mma<1,0>, cudaFuncAttributeMaxDynamicSharedMemorySize, GM_SMEM);
    cudaFuncSetAttribute(gemm_mma<2,1>, cudaFuncAttributeMaxDynamicSharedMemorySize, GM_SMEM);
    cudaFuncSetAttribute(flash_mma, cudaFuncAttributeMaxDynamicSharedMemorySize, FA_SMEM);

    // weight conversions: ONE launch
    convAll<<<7680, dim3(32, 8)>>>(q_U, k_U, v_U, out_U, out_V, fc1_U, fc1_V, fc2_U, fc2_V,
                                   Wqkv, Wou, Wov, Wf1u, Wf1v, Wf2u, Wf2v);

    // 1. LN1 -> fp16
    ln_half<<<NROW, 256>>>(hidden, A16, ln1_g, ln1_b);
    // 2. fused qkv rank projection -> fp16 [4096, 1536]
    gemm_mma<0,1><<<dim3(HR3/128, NROW/128), 256, GM_SMEM>>>(A16, Wqkv, nullptr, R16,
        nullptr, nullptr, NROW, HR3, DD);
    // 3. per-head expansion
    expand3<<<dim3(SS/64, BB*HH, 3), 256>>>(R16, q_V, k_V, v_V, q_b, k_b, v_b,
                                            Q16, K16, V16);
    // 4. flash attention -> merged-head fp16 Y in C16
    flash_mma<<<dim3(SS/128, BB*HH), 256, FA_SMEM>>>(Q16, K16, V16, C16);
    // 5. out projection + residual
    gemm_mma<0,1><<<dim3(R_OUT/128, NROW/128), 256, GM_SMEM>>>(C16, Wou, nullptr, A16,
        nullptr, nullptr, NROW, R_OUT, DD);
    gemm_mma<1,0><<<dim3(DD/128, NROW/128), 256, GM_SMEM>>>(A16, Wov, hb, nullptr,
        out_b, hidden, NROW, DD, R_OUT);
    // 6. LN2 -> fp16
    ln_half<<<NROW, 256>>>(hb, C16, ln2_g, ln2_b);
    // 7. MLP
    gemm_mma<0,1><<<dim3(R_FC/128, NROW/128), 256, GM_SMEM>>>(C16, Wf1u, nullptr, A16,
        nullptr, nullptr, NROW, R_FC, DD);
    gemm_mma<2,1><<<dim3(II/128, NROW/128), 256, GM_SMEM>>>(A16, Wf1v, nullptr, C16,
        fc1_b, nullptr, NROW, II, R_FC);
    gemm_mma<0,1><<<dim3(R_FC/128, NROW/128), 256, GM_SMEM>>>(C16, Wf2u, nullptr, A16,
        nullptr, nullptr, NROW, R_FC, II);
    gemm_mma<1,0><<<dim3(DD/128, NROW/128), 256, GM_SMEM>>>(A16, Wf2v, out, nullptr,
        fc2_b, hb, NROW, DD, R_FC);
}